// round 2
// baseline (speedup 1.0000x reference)
#include <cuda_runtime.h>
#include <cuda_bf16.h>
#include <math.h>

// Problem constants
#define BB 4
#define TT 1024
#define HH 4
#define NN_ 4096
#define DD 256
#define DH 1024
#define LL 6
#define VV 256
#define EPS 1e-5f

// ---------------------------------------------------------------------------
// Scratch buffers (device globals; no allocation allowed)
// ---------------------------------------------------------------------------
__device__ float g_v[BB * TT * DD];          //  4 MB
__device__ float g_x[BB * HH * TT * DH];     // 64 MB
__device__ float g_xr[BB * HH * TT * DH];    // 64 MB
__device__ float g_scores[BB * HH * TT * TT];// 64 MB
__device__ float g_a[BB * HH * TT * DD];     // 16 MB
__device__ float g_ye[BB * TT * NN_];        // 64 MB
__device__ float g_z[BB * TT * DD];          //  4 MB
__device__ float g_cos[TT * DH];             //  4 MB
__device__ float g_sin[TT * DH];             //  4 MB

// ---------------------------------------------------------------------------
// Block reduction helper (256 threads)
// ---------------------------------------------------------------------------
__device__ __forceinline__ float block_sum_256(float v, float* smem) {
    #pragma unroll
    for (int o = 16; o > 0; o >>= 1) v += __shfl_down_sync(0xffffffffu, v, o);
    int w = threadIdx.x >> 5, l = threadIdx.x & 31;
    if (l == 0) smem[w] = v;
    __syncthreads();
    if (w == 0) {
        float s = (l < 8) ? smem[l] : 0.0f;
        #pragma unroll
        for (int o = 4; o > 0; o >>= 1) s += __shfl_down_sync(0xffffffffu, s, o);
        if (l == 0) smem[0] = s;
    }
    __syncthreads();
    float r = smem[0];
    __syncthreads();
    return r;
}

// ---------------------------------------------------------------------------
// RoPE tables: cos/sin [T, Dh]; computed in double so our table error is
// negligible vs the reference's own fp32 rounding.
// ---------------------------------------------------------------------------
__global__ void rope_tables_kernel(float* cosT, float* sinT) {
    int t = blockIdx.x;           // 0..T-1
    int j = threadIdx.x;          // 0..511
    double expnt = (2.0 * (double)j) / (double)DH;
    double inv = pow(10000.0, -expnt);
    double phase = (double)t * inv;
    float c = (float)cos(phase);
    float s = (float)sin(phase);
    cosT[t * DH + j]       = c;
    cosT[t * DH + 512 + j] = c;
    sinT[t * DH + j]       = s;
    sinT[t * DH + 512 + j] = s;
}

// ---------------------------------------------------------------------------
// Embedding gather + LayerNorm (no affine). One block per token, 256 threads.
// ---------------------------------------------------------------------------
__global__ void embed_ln_kernel(const int* __restrict__ tokens,
                                const float* __restrict__ emb_w,
                                float* __restrict__ v) {
    __shared__ float smem[8];
    int bt = blockIdx.x;
    int d = threadIdx.x;
    int tok = tokens[bt];
    float val = emb_w[tok * DD + d];
    float m = block_sum_256(val, smem) * (1.0f / DD);
    float c = val - m;
    float var = block_sum_256(c * c, smem) * (1.0f / DD);
    v[bt * DD + d] = c * rsqrtf(var + EPS);
}

// ---------------------------------------------------------------------------
// RoPE apply: xr = x*cos + rotate_half(x)*sin, elementwise over [B,H,T,Dh].
// ---------------------------------------------------------------------------
__global__ void rope_apply_kernel(const float* __restrict__ x,
                                  const float* __restrict__ cosT,
                                  const float* __restrict__ sinT,
                                  float* __restrict__ xr) {
    long idx = (long)blockIdx.x * blockDim.x + threadIdx.x;
    int e = (int)(idx & (DH - 1));
    int t = (int)((idx >> 10) & (TT - 1));
    float xv = x[idx];
    float other = (e < 512) ? -x[idx + 512] : x[idx - 512];
    xr[idx] = xv * cosT[t * DH + e] + other * sinT[t * DH + e];
}

// ---------------------------------------------------------------------------
// Residual: v = LN(v + LN(z)). One block per token.
// ---------------------------------------------------------------------------
__global__ void fuse_ln_kernel(const float* __restrict__ z,
                               float* __restrict__ v) {
    __shared__ float smem[8];
    int bt = blockIdx.x;
    int d = threadIdx.x;
    float u = z[bt * DD + d];
    float m1 = block_sum_256(u, smem) * (1.0f / DD);
    float c1 = u - m1;
    float var1 = block_sum_256(c1 * c1, smem) * (1.0f / DD);
    float lnz = c1 * rsqrtf(var1 + EPS);
    float w = v[bt * DD + d] + lnz;
    float m2 = block_sum_256(w, smem) * (1.0f / DD);
    float c2 = w - m2;
    float var2 = block_sum_256(c2 * c2, smem) * (1.0f / DD);
    v[bt * DD + d] = c2 * rsqrtf(var2 + EPS);
}

// ---------------------------------------------------------------------------
// Generic batched SGEMM: C = op(A @ B) with optional epilogues.
//   EPI 0: C = acc
//   EPI 1: C = relu(acc)
//   EPI 2: C = relu(acc) * AUX   (AUX offset = z * sAux)
// Batch offsets: off = (z/div)*s1 + (z%div)*s2 for each of A,B,C.
// TRANSB: B is stored [N,K] row-major (access B[n*ldb + k]).
// 128x128x8 tile, 256 threads, 8x8 per-thread microtile. All dims must be
// multiples of 128 (M,N) and 8 (K) — true for every GEMM here.
// ---------------------------------------------------------------------------
template <int EPI, bool TRANSB>
__global__ void __launch_bounds__(256, 2)
sgemm_kernel(const float* __restrict__ A, const float* __restrict__ B,
             float* __restrict__ C, const float* __restrict__ AUX,
             int M, int N, int K, int lda, int ldb, int ldc, int ldaux,
             int divA, long sA1, long sA2,
             int divB, long sB1, long sB2,
             int divC, long sC1, long sC2,
             long sAux) {
    const int z = blockIdx.z;
    A += (long)(z / divA) * sA1 + (long)(z % divA) * sA2;
    B += (long)(z / divB) * sB1 + (long)(z % divB) * sB2;
    C += (long)(z / divC) * sC1 + (long)(z % divC) * sC2;
    if (EPI == 2) AUX += (long)z * sAux;

    __shared__ float As[8][128];
    __shared__ float Bs[8][128];

    const int tid = threadIdx.x;
    const int tx = tid & 15;
    const int ty = tid >> 4;
    const int rowBase = blockIdx.y * 128;
    const int colBase = blockIdx.x * 128;

    float acc[8][8];
    #pragma unroll
    for (int i = 0; i < 8; i++)
        #pragma unroll
        for (int j = 0; j < 8; j++) acc[i][j] = 0.0f;

    const int aRow = tid >> 1;
    const int aK = (tid & 1) * 4;
    const float* Aptr = A + (long)(rowBase + aRow) * lda + aK;
    const float* Bptr;
    if (!TRANSB)
        Bptr = B + (long)(tid >> 5) * ldb + colBase + (tid & 31) * 4;
    else
        Bptr = B + (long)(colBase + (tid >> 1)) * ldb + (tid & 1) * 4;

    for (int k0 = 0; k0 < K; k0 += 8) {
        float4 av = *(const float4*)Aptr;
        As[aK + 0][aRow] = av.x;
        As[aK + 1][aRow] = av.y;
        As[aK + 2][aRow] = av.z;
        As[aK + 3][aRow] = av.w;
        if (!TRANSB) {
            float4 bv = *(const float4*)Bptr;
            *(float4*)&Bs[tid >> 5][(tid & 31) * 4] = bv;
        } else {
            float4 bv = *(const float4*)Bptr;
            int n = tid >> 1, kk = (tid & 1) * 4;
            Bs[kk + 0][n] = bv.x;
            Bs[kk + 1][n] = bv.y;
            Bs[kk + 2][n] = bv.z;
            Bs[kk + 3][n] = bv.w;
        }
        __syncthreads();
        #pragma unroll
        for (int kk = 0; kk < 8; kk++) {
            float af[8], bf[8];
            *(float4*)(af)     = *(const float4*)&As[kk][ty * 4];
            *(float4*)(af + 4) = *(const float4*)&As[kk][64 + ty * 4];
            *(float4*)(bf)     = *(const float4*)&Bs[kk][tx * 4];
            *(float4*)(bf + 4) = *(const float4*)&Bs[kk][64 + tx * 4];
            #pragma unroll
            for (int i = 0; i < 8; i++)
                #pragma unroll
                for (int j = 0; j < 8; j++)
                    acc[i][j] = fmaf(af[i], bf[j], acc[i][j]);
        }
        __syncthreads();
        Aptr += 8;
        if (!TRANSB) Bptr += 8 * (long)ldb;
        else Bptr += 8;
    }

    #pragma unroll
    for (int i = 0; i < 8; i++) {
        int r = rowBase + (i < 4 ? ty * 4 + i : 64 + ty * 4 + (i - 4));
        #pragma unroll
        for (int j = 0; j < 8; j++) {
            int c = colBase + (j < 4 ? tx * 4 + j : 64 + tx * 4 + (j - 4));
            float val = acc[i][j];
            if (EPI == 1) val = fmaxf(val, 0.0f);
            if (EPI == 2) val = fmaxf(val, 0.0f) * AUX[(long)r * ldaux + c];
            C[(long)r * ldc + c] = val;
        }
    }
}

// ---------------------------------------------------------------------------
// Host launcher
// ---------------------------------------------------------------------------
extern "C" void kernel_launch(void* const* d_in, const int* in_sizes, int n_in,
                              void* d_out, int out_size) {
    const int*   tokens  = (const int*)d_in[0];
    const float* emb_w   = (const float*)d_in[1];
    const float* E       = (const float*)d_in[2];
    const float* Dx      = (const float*)d_in[3];
    const float* Dy      = (const float*)d_in[4];
    const float* readout = (const float*)d_in[5];
    float* out = (float*)d_out;

    float *v, *x, *xr, *scores, *a, *ye, *zb, *cosT, *sinT;
    cudaGetSymbolAddress((void**)&v, g_v);
    cudaGetSymbolAddress((void**)&x, g_x);
    cudaGetSymbolAddress((void**)&xr, g_xr);
    cudaGetSymbolAddress((void**)&scores, g_scores);
    cudaGetSymbolAddress((void**)&a, g_a);
    cudaGetSymbolAddress((void**)&ye, g_ye);
    cudaGetSymbolAddress((void**)&zb, g_z);
    cudaGetSymbolAddress((void**)&cosT, g_cos);
    cudaGetSymbolAddress((void**)&sinT, g_sin);

    // RoPE tables + embedding LN
    rope_tables_kernel<<<TT, 512>>>(cosT, sinT);
    embed_ln_kernel<<<BB * TT, 256>>>(tokens, emb_w, v);

    const long TDh = (long)TT * DH;   // per-(b,h) x/xr stride
    const long TD  = (long)TT * DD;   // per-b v stride
    const long T2  = (long)TT * TT;   // per-(b,h) scores stride
    const long DDh = (long)DD * DH;   // per-h Dx/Dy stride
    const long TN  = (long)TT * NN_;  // per-b ye stride

    for (int l = 0; l < LL; l++) {
        // 1) x = relu(v @ Dx_h), per (b,h): M=T, N=Dh, K=D
        sgemm_kernel<1, false><<<dim3(DH / 128, TT / 128, BB * HH), 256>>>(
            v, Dx, x, nullptr,
            TT, DH, DD, DD, DH, DH, 0,
            HH, TD, 0,      // A: v, off=(z/H)*T*D
            HH, 0, DDh,     // B: Dx, off=(z%H)*D*Dh
            1, TDh, 0,      // C: x, off=z*T*Dh
            0);

        // 2) RoPE
        rope_apply_kernel<<<(BB * HH * TT * DH) / 256, 256>>>(x, cosT, sinT, xr);

        // 3) scores = xr @ xr^T, per (b,h): M=N=T, K=Dh  (TRANSB)
        sgemm_kernel<0, true><<<dim3(TT / 128, TT / 128, BB * HH), 256>>>(
            xr, xr, scores, nullptr,
            TT, TT, DH, DH, DH, TT, 0,
            1, TDh, 0,
            1, TDh, 0,
            1, T2, 0,
            0);

        // 4) a = scores @ v_b, per (b,h): M=T, N=D, K=T
        sgemm_kernel<0, false><<<dim3(DD / 128, TT / 128, BB * HH), 256>>>(
            scores, v, a, nullptr,
            TT, DD, TT, TT, DD, DD, 0,
            1, T2, 0,
            HH, TD, 0,
            1, TD, 0,
            0);

        // 5) ye[b,t,h*Dh+e] = relu(a @ Dy_h) * x, per (b,h): M=T, N=Dh, K=D
        sgemm_kernel<2, false><<<dim3(DH / 128, TT / 128, BB * HH), 256>>>(
            a, Dy, ye, x,
            TT, DH, DD, DD, DH, NN_, DH,
            1, TD, 0,
            HH, 0, DDh,
            HH, TN, DH,     // C: off=(z/H)*T*N + (z%H)*Dh
            TDh);

        // 6) z = ye @ E, flat: M=B*T, N=D, K=N
        sgemm_kernel<0, false><<<dim3(DD / 128, (BB * TT) / 128, 1), 256>>>(
            ye, E, zb, nullptr,
            BB * TT, DD, NN_, NN_, DD, DD, 0,
            1, 0, 0, 1, 0, 0, 1, 0, 0, 0);

        // 7) v = LN(v + LN(z))
        fuse_ln_kernel<<<BB * TT, 256>>>(zb, v);
    }

    // out = v @ readout: M=B*T, N=V, K=D
    sgemm_kernel<0, false><<<dim3(VV / 128, (BB * TT) / 128, 1), 256>>>(
        v, readout, out, nullptr,
        BB * TT, VV, DD, DD, VV, VV, 0,
        1, 0, 0, 1, 0, 0, 1, 0, 0, 0);
}

// round 5
// speedup vs baseline: 1.8222x; 1.8222x over previous
#include <cuda_runtime.h>
#include <cuda_bf16.h>
#include <math.h>
#include <stdint.h>

// Problem constants
#define BB 4
#define TT 1024
#define HH 4
#define NN_ 4096
#define DD 256
#define DH 1024
#define LL 6
#define VV 256
#define EPS 1e-5f

// ---------------------------------------------------------------------------
// Scratch buffers (device globals; no allocation allowed)
// ---------------------------------------------------------------------------
__device__ float g_v[BB * TT * DD];
__device__ float g_x[BB * HH * TT * DH];
__device__ float g_xr[BB * HH * TT * DH];
__device__ float g_scores[BB * HH * TT * TT];
__device__ float g_a[BB * HH * TT * DD];
__device__ float g_ye[BB * TT * NN_];
__device__ float g_z[BB * TT * DD];
__device__ float g_cos[TT * DH];
__device__ float g_sin[TT * DH];

// ---------------------------------------------------------------------------
// tf32 helpers
// ---------------------------------------------------------------------------
__device__ __forceinline__ float to_tf32(float x) {
    uint32_t y;
    asm("cvt.rna.tf32.f32 %0, %1;" : "=r"(y) : "f"(x));
    return __uint_as_float(y);
}

// mma.sync m16n8k8 tf32: d += a @ b  (row.col)
__device__ __forceinline__ void mma_tf32(float* d, const uint32_t* a, const uint32_t* b) {
    asm volatile(
        "mma.sync.aligned.m16n8k8.row.col.f32.tf32.tf32.f32 "
        "{%0,%1,%2,%3}, {%4,%5,%6,%7}, {%8,%9}, {%0,%1,%2,%3};"
        : "+f"(d[0]), "+f"(d[1]), "+f"(d[2]), "+f"(d[3])
        : "r"(a[0]), "r"(a[1]), "r"(a[2]), "r"(a[3]), "r"(b[0]), "r"(b[1]));
}

// ---------------------------------------------------------------------------
// Warp-MMA tf32 batched GEMM: C = epi(A @ B^T) per 128x128 CTA tile.
//   A: [M, K] row-major (lda).
//   B: BTRANS=false -> [N, K] row-major (ldb);
//      BTRANS=true  -> [K, N] row-major (ldb), transposed on load.
//   EPI 0: C=acc; 1: C=relu(acc); 2: C=relu(acc)*AUX.
// 256 threads = 8 warps (2x4), warp tile 64x32, K-stage 16, double-buffered.
// SMEM rows padded to 20 floats -> conflict-free fragment LDS.
// ---------------------------------------------------------------------------
template <int EPI, bool BTRANS>
__global__ void __launch_bounds__(256)
mm_mma_kernel(const float* __restrict__ A, const float* __restrict__ B,
              float* __restrict__ C, const float* __restrict__ AUX,
              int K, int lda, int ldb, int ldc, int ldaux,
              int divA, long sA1, long sA2,
              int divB, long sB1, long sB2,
              int divC, long sC1, long sC2,
              long sAux) {
    __shared__ float As[2][128][20];
    __shared__ float Bs[2][128][20];

    const int tid = threadIdx.x;
    const int wid = tid >> 5;
    const int lane = tid & 31;
    const int g = lane >> 2;    // octet row/col group
    const int tig = lane & 3;   // thread-in-group
    const int wr = wid >> 2;    // warp row 0..1 (64 rows each)
    const int wc = wid & 3;     // warp col 0..3 (32 cols each)

    const int z = blockIdx.z;
    A += (long)(z / divA) * sA1 + (long)(z % divA) * sA2;
    B += (long)(z / divB) * sB1 + (long)(z % divB) * sB2;
    C += (long)(z / divC) * sC1 + (long)(z % divC) * sC2;
    if (EPI == 2) AUX += (long)z * sAux;
    const int rowBase = blockIdx.y * 128;
    const int colBase = blockIdx.x * 128;

    // gmem staging indices
    const int aRow = tid >> 2;      // 0..63 (and +64)
    const int aKg = tid & 3;        // float4 within 16-float K-stage
    const int bK = tid >> 5;        // 0..7 (and +8)     [BTRANS]
    const int bN4 = tid & 31;       // float4 along n    [BTRANS]

    float4 ra[2], rb[2];
    float acc[4][4][4];
    #pragma unroll
    for (int i = 0; i < 4; i++)
        #pragma unroll
        for (int j = 0; j < 4; j++)
            #pragma unroll
            for (int k = 0; k < 4; k++) acc[i][j][k] = 0.0f;

    const int nStages = K >> 4;

    auto load_regs = [&](int c) {
        const int k0 = c << 4;
        #pragma unroll
        for (int i = 0; i < 2; i++)
            ra[i] = *(const float4*)(A + (long)(rowBase + aRow + 64 * i) * lda + k0 + aKg * 4);
        if (!BTRANS) {
            #pragma unroll
            for (int i = 0; i < 2; i++)
                rb[i] = *(const float4*)(B + (long)(colBase + aRow + 64 * i) * ldb + k0 + aKg * 4);
        } else {
            #pragma unroll
            for (int i = 0; i < 2; i++)
                rb[i] = *(const float4*)(B + (long)(k0 + bK + 8 * i) * ldb + colBase + bN4 * 4);
        }
    };
    auto store_smem = [&](int s) {
        #pragma unroll
        for (int i = 0; i < 2; i++) {
            float* p = &As[s][aRow + 64 * i][aKg * 4];
            p[0] = to_tf32(ra[i].x); p[1] = to_tf32(ra[i].y);
            p[2] = to_tf32(ra[i].z); p[3] = to_tf32(ra[i].w);
        }
        if (!BTRANS) {
            #pragma unroll
            for (int i = 0; i < 2; i++) {
                float* p = &Bs[s][aRow + 64 * i][aKg * 4];
                p[0] = to_tf32(rb[i].x); p[1] = to_tf32(rb[i].y);
                p[2] = to_tf32(rb[i].z); p[3] = to_tf32(rb[i].w);
            }
        } else {
            #pragma unroll
            for (int i = 0; i < 2; i++) {
                int kk = bK + 8 * i;
                Bs[s][bN4 * 4 + 0][kk] = to_tf32(rb[i].x);
                Bs[s][bN4 * 4 + 1][kk] = to_tf32(rb[i].y);
                Bs[s][bN4 * 4 + 2][kk] = to_tf32(rb[i].z);
                Bs[s][bN4 * 4 + 3][kk] = to_tf32(rb[i].w);
            }
        }
    };
    auto compute = [&](int s) {
        #pragma unroll
        for (int ks = 0; ks < 2; ks++) {
            const int kk = ks * 8;
            uint32_t afr[4][4], bfr[4][2];
            #pragma unroll
            for (int ms = 0; ms < 4; ms++) {
                const int r0 = wr * 64 + ms * 16 + g;
                afr[ms][0] = __float_as_uint(As[s][r0][kk + tig]);
                afr[ms][1] = __float_as_uint(As[s][r0 + 8][kk + tig]);
                afr[ms][2] = __float_as_uint(As[s][r0][kk + tig + 4]);
                afr[ms][3] = __float_as_uint(As[s][r0 + 8][kk + tig + 4]);
            }
            #pragma unroll
            for (int ns = 0; ns < 4; ns++) {
                const int n0 = wc * 32 + ns * 8 + g;
                bfr[ns][0] = __float_as_uint(Bs[s][n0][kk + tig]);
                bfr[ns][1] = __float_as_uint(Bs[s][n0][kk + tig + 4]);
            }
            #pragma unroll
            for (int ms = 0; ms < 4; ms++)
                #pragma unroll
                for (int ns = 0; ns < 4; ns++)
                    mma_tf32(acc[ms][ns], afr[ms], bfr[ns]);
        }
    };

    load_regs(0);
    store_smem(0);
    __syncthreads();
    for (int c = 0; c < nStages; c++) {
        if (c + 1 < nStages) load_regs(c + 1);
        compute(c & 1);
        if (c + 1 < nStages) {
            store_smem((c + 1) & 1);
            __syncthreads();
        }
    }

    // Epilogue: c0/c1 at (row g, cols 2tig,2tig+1), c2/c3 at row g+8.
    #pragma unroll
    for (int ms = 0; ms < 4; ms++) {
        const int r = rowBase + wr * 64 + ms * 16 + g;
        #pragma unroll
        for (int ns = 0; ns < 4; ns++) {
            const int col = colBase + wc * 32 + ns * 8 + tig * 2;
            float2 v0 = make_float2(acc[ms][ns][0], acc[ms][ns][1]);
            float2 v1 = make_float2(acc[ms][ns][2], acc[ms][ns][3]);
            if (EPI >= 1) {
                v0.x = fmaxf(v0.x, 0.0f); v0.y = fmaxf(v0.y, 0.0f);
                v1.x = fmaxf(v1.x, 0.0f); v1.y = fmaxf(v1.y, 0.0f);
            }
            if (EPI == 2) {
                float2 a0 = *(const float2*)(AUX + (long)r * ldaux + col);
                float2 a1 = *(const float2*)(AUX + (long)(r + 8) * ldaux + col);
                v0.x *= a0.x; v0.y *= a0.y;
                v1.x *= a1.x; v1.y *= a1.y;
            }
            *(float2*)(C + (long)r * ldc + col) = v0;
            *(float2*)(C + (long)(r + 8) * ldc + col) = v1;
        }
    }
}

// ---------------------------------------------------------------------------
// Elementwise kernels
// ---------------------------------------------------------------------------
__device__ __forceinline__ float block_sum_256(float v, float* smem) {
    #pragma unroll
    for (int o = 16; o > 0; o >>= 1) v += __shfl_down_sync(0xffffffffu, v, o);
    int w = threadIdx.x >> 5, l = threadIdx.x & 31;
    if (l == 0) smem[w] = v;
    __syncthreads();
    if (w == 0) {
        float s = (l < 8) ? smem[l] : 0.0f;
        #pragma unroll
        for (int o = 4; o > 0; o >>= 1) s += __shfl_down_sync(0xffffffffu, s, o);
        if (l == 0) smem[0] = s;
    }
    __syncthreads();
    float r = smem[0];
    __syncthreads();
    return r;
}

__global__ void rope_tables_kernel(float* cosT, float* sinT) {
    int t = blockIdx.x;
    int j = threadIdx.x;
    double expnt = (2.0 * (double)j) / (double)DH;
    double inv = pow(10000.0, -expnt);
    double phase = (double)t * inv;
    float c = (float)cos(phase);
    float s = (float)sin(phase);
    cosT[t * DH + j] = c;  cosT[t * DH + 512 + j] = c;
    sinT[t * DH + j] = s;  sinT[t * DH + 512 + j] = s;
}

__global__ void embed_ln_kernel(const int* __restrict__ tokens,
                                const float* __restrict__ emb_w,
                                float* __restrict__ v) {
    __shared__ float smem[8];
    int bt = blockIdx.x;
    int d = threadIdx.x;
    int tok = tokens[bt];
    float val = emb_w[tok * DD + d];
    float m = block_sum_256(val, smem) * (1.0f / DD);
    float c = val - m;
    float var = block_sum_256(c * c, smem) * (1.0f / DD);
    v[bt * DD + d] = c * rsqrtf(var + EPS);
}

__global__ void rope_apply_kernel(const float* __restrict__ x,
                                  const float* __restrict__ cosT,
                                  const float* __restrict__ sinT,
                                  float* __restrict__ xr) {
    long idx = (long)blockIdx.x * blockDim.x + threadIdx.x;
    int e = (int)(idx & (DH - 1));
    int t = (int)((idx >> 10) & (TT - 1));
    float xv = x[idx];
    float other = (e < 512) ? -x[idx + 512] : x[idx - 512];
    xr[idx] = xv * cosT[t * DH + e] + other * sinT[t * DH + e];
}

__global__ void fuse_ln_kernel(const float* __restrict__ z,
                               float* __restrict__ v) {
    __shared__ float smem[8];
    int bt = blockIdx.x;
    int d = threadIdx.x;
    float u = z[bt * DD + d];
    float m1 = block_sum_256(u, smem) * (1.0f / DD);
    float c1 = u - m1;
    float var1 = block_sum_256(c1 * c1, smem) * (1.0f / DD);
    float lnz = c1 * rsqrtf(var1 + EPS);
    float w = v[bt * DD + d] + lnz;
    float m2 = block_sum_256(w, smem) * (1.0f / DD);
    float c2 = w - m2;
    float var2 = block_sum_256(c2 * c2, smem) * (1.0f / DD);
    v[bt * DD + d] = c2 * rsqrtf(var2 + EPS);
}

// ---------------------------------------------------------------------------
// Host launcher
// ---------------------------------------------------------------------------
extern "C" void kernel_launch(void* const* d_in, const int* in_sizes, int n_in,
                              void* d_out, int out_size) {
    const int*   tokens  = (const int*)d_in[0];
    const float* emb_w   = (const float*)d_in[1];
    const float* E       = (const float*)d_in[2];
    const float* Dx      = (const float*)d_in[3];
    const float* Dy      = (const float*)d_in[4];
    const float* readout = (const float*)d_in[5];
    float* out = (float*)d_out;

    float *v, *x, *xr, *scores, *a, *ye, *zb, *cosT, *sinT;
    cudaGetSymbolAddress((void**)&v, g_v);
    cudaGetSymbolAddress((void**)&x, g_x);
    cudaGetSymbolAddress((void**)&xr, g_xr);
    cudaGetSymbolAddress((void**)&scores, g_scores);
    cudaGetSymbolAddress((void**)&a, g_a);
    cudaGetSymbolAddress((void**)&ye, g_ye);
    cudaGetSymbolAddress((void**)&zb, g_z);
    cudaGetSymbolAddress((void**)&cosT, g_cos);
    cudaGetSymbolAddress((void**)&sinT, g_sin);

    rope_tables_kernel<<<TT, 512>>>(cosT, sinT);
    embed_ln_kernel<<<BB * TT, 256>>>(tokens, emb_w, v);

    const long TDh = (long)TT * DH;
    const long TD  = (long)TT * DD;
    const long T2  = (long)TT * TT;
    const long DDh = (long)DD * DH;
    const long TN  = (long)TT * NN_;

    for (int l = 0; l < LL; l++) {
        // 1) x = relu(v @ Dx_h): A=v [T,D], B=Dx_h [D,Dh] (trans), M=T N=Dh K=D
        mm_mma_kernel<1, true><<<dim3(DH / 128, TT / 128, BB * HH), 256>>>(
            v, Dx, x, nullptr,
            DD, DD, DH, DH, 0,
            HH, TD, 0,   HH, 0, DDh,   1, TDh, 0,   0);

        // 2) RoPE
        rope_apply_kernel<<<(BB * HH * TT * DH) / 256, 256>>>(x, cosT, sinT, xr);

        // 3) scores = xr @ xr^T: A=B=xr [T,Dh], M=N=T K=Dh
        mm_mma_kernel<0, false><<<dim3(TT / 128, TT / 128, BB * HH), 256>>>(
            xr, xr, scores, nullptr,
            DH, DH, DH, TT, 0,
            1, TDh, 0,   1, TDh, 0,   1, T2, 0,   0);

        // 4) a = scores @ v_b: A=scores [T,T], B=v [T,D] (trans), M=T N=D K=T
        mm_mma_kernel<0, true><<<dim3(DD / 128, TT / 128, BB * HH), 256>>>(
            scores, v, a, nullptr,
            TT, TT, DD, DD, 0,
            1, T2, 0,   HH, TD, 0,   1, TD, 0,   0);

        // 5) ye = relu(a @ Dy_h) * x: A=a [T,D], B=Dy_h [D,Dh] (trans), M=T N=Dh K=D
        mm_mma_kernel<2, true><<<dim3(DH / 128, TT / 128, BB * HH), 256>>>(
            a, Dy, ye, x,
            DD, DD, DH, NN_, DH,
            1, TD, 0,   HH, 0, DDh,   HH, TN, DH,   TDh);

        // 6) z = ye @ E: A=ye [B*T,N], B=E [N,D] (trans), M=B*T N=D K=N
        mm_mma_kernel<0, true><<<dim3(DD / 128, (BB * TT) / 128, 1), 256>>>(
            ye, E, zb, nullptr,
            NN_, NN_, DD, DD, 0,
            1, 0, 0,   1, 0, 0,   1, 0, 0,   0);

        // 7) v = LN(v + LN(z))
        fuse_ln_kernel<<<BB * TT, 256>>>(zb, v);
    }

    // out = v @ readout: A=v [B*T,D], B=readout [D,V] (trans), M=B*T N=V K=D
    mm_mma_kernel<0, true><<<dim3(VV / 128, (BB * TT) / 128, 1), 256>>>(
        v, readout, out, nullptr,
        DD, DD, VV, VV, 0,
        1, 0, 0,   1, 0, 0,   1, 0, 0,   0);
}

// round 6
// speedup vs baseline: 3.8356x; 2.1049x over previous
#include <cuda_runtime.h>
#include <cuda_bf16.h>
#include <math.h>
#include <stdint.h>

// Problem constants
#define BB 4
#define TT 1024
#define HH 4
#define NN_ 4096
#define DD 256
#define DH 1024
#define LL 6
#define VV 256
#define EPS 1e-5f

// ---------------------------------------------------------------------------
// Scratch buffers (device globals; no allocation allowed)
// ---------------------------------------------------------------------------
__device__ float g_v[BB * TT * DD];
__device__ float g_x[BB * HH * TT * DH];
__device__ float g_xr[BB * HH * TT * DH];
__device__ float g_w2[BB * HH * DD * DH];
__device__ float g_a[BB * HH * TT * DD];
__device__ float g_ye[BB * TT * NN_];
__device__ float g_z[4 * BB * TT * DD];     // split-K partials
__device__ float g_cos[TT * DH];
__device__ float g_sin[TT * DH];

// bf16 hi/lo split operand buffers
__device__ __nv_bfloat16 s_v_hi[BB * TT * DD],   s_v_lo[BB * TT * DD];
__device__ __nv_bfloat16 s_xr_hi[BB * HH * TT * DH], s_xr_lo[BB * HH * TT * DH];
__device__ __nv_bfloat16 s_w2_hi[BB * HH * DD * DH], s_w2_lo[BB * HH * DD * DH];
__device__ __nv_bfloat16 s_a_hi[BB * HH * TT * DD],  s_a_lo[BB * HH * TT * DD];
__device__ __nv_bfloat16 s_ye_hi[BB * TT * NN_], s_ye_lo[BB * TT * NN_];
__device__ __nv_bfloat16 s_dx_hi[HH * DD * DH],  s_dx_lo[HH * DD * DH];
__device__ __nv_bfloat16 s_dy_hi[HH * DD * DH],  s_dy_lo[HH * DD * DH];
__device__ __nv_bfloat16 s_e_hi[NN_ * DD],       s_e_lo[NN_ * DD];
__device__ __nv_bfloat16 s_ro_hi[DD * VV],       s_ro_lo[DD * VV];

// ---------------------------------------------------------------------------
// PTX helpers
// ---------------------------------------------------------------------------
__device__ __forceinline__ uint32_t smem_to_u32(const void* p) {
    uint32_t a;
    asm("{ .reg .u64 t; cvta.to.shared.u64 t, %1; cvt.u32.u64 %0, t; }" : "=r"(a) : "l"(p));
    return a;
}
__device__ __forceinline__ void cp16(uint32_t dst, const void* src) {
    asm volatile("cp.async.cg.shared.global [%0], [%1], 16;" :: "r"(dst), "l"(src));
}
#define CP_COMMIT() asm volatile("cp.async.commit_group;" ::: "memory")
#define CP_WAIT0() asm volatile("cp.async.wait_group 0;" ::: "memory")
#define CP_WAIT1() asm volatile("cp.async.wait_group 1;" ::: "memory")

__device__ __forceinline__ void ldsm_x4(uint32_t* r, uint32_t addr) {
    asm volatile("ldmatrix.sync.aligned.m8n8.x4.shared.b16 {%0,%1,%2,%3}, [%4];"
                 : "=r"(r[0]), "=r"(r[1]), "=r"(r[2]), "=r"(r[3]) : "r"(addr));
}
__device__ __forceinline__ void ldsm_x4_t(uint32_t* r, uint32_t addr) {
    asm volatile("ldmatrix.sync.aligned.m8n8.x4.trans.shared.b16 {%0,%1,%2,%3}, [%4];"
                 : "=r"(r[0]), "=r"(r[1]), "=r"(r[2]), "=r"(r[3]) : "r"(addr));
}
__device__ __forceinline__ void mma_bf16(float* d, const uint32_t* a, const uint32_t* b) {
    asm volatile(
        "mma.sync.aligned.m16n8k16.row.col.f32.bf16.bf16.f32 "
        "{%0,%1,%2,%3}, {%4,%5,%6,%7}, {%8,%9}, {%0,%1,%2,%3};"
        : "+f"(d[0]), "+f"(d[1]), "+f"(d[2]), "+f"(d[3])
        : "r"(a[0]), "r"(a[1]), "r"(a[2]), "r"(a[3]), "r"(b[0]), "r"(b[1]));
}

// ---------------------------------------------------------------------------
// bf16x3 GEMM: C = epi(A @ B^T), 128x128 CTA tile, 8 warps (2x4), K-stage 32.
//   A arrays: ATR=false -> [M,K] (lda = K-row stride); ATR=true -> [K,M] (lda).
//   B arrays: BTR=false -> [N,K]; BTR=true -> [K,N].
//   EPI 0: C=acc; 1: relu; 2: relu*AUX.
// SMEM: 16 tiles of 4KB (buf2 x {A,B} x sub2 x {hi,lo}), XOR-swizzled,
// fragments via ldmatrix (trans variant for [K,*] layouts).
// ---------------------------------------------------------------------------
#define TILE_B 4096
__device__ __forceinline__ uint32_t tile_addr(uint32_t sb, int buf, int ab, int sub, int hl) {
    return sb + (uint32_t)((((buf * 2 + ab) * 2 + sub) * 2 + hl) * TILE_B);
}

template <int EPI, bool ATR, bool BTR>
__global__ void __launch_bounds__(256)
mm_bf16x3_kernel(const __nv_bfloat16* __restrict__ Ahi, const __nv_bfloat16* __restrict__ Alo,
                 const __nv_bfloat16* __restrict__ Bhi, const __nv_bfloat16* __restrict__ Blo,
                 float* __restrict__ C, const float* __restrict__ AUX,
                 int K, int lda, int ldb, int ldc, int ldaux,
                 int divA, long sA1, long sA2,
                 int divB, long sB1, long sB2,
                 int divC, long sC1, long sC2,
                 long sAux) {
    extern __shared__ char smem[];
    const uint32_t sb = smem_to_u32(smem);
    const int tid = threadIdx.x;
    const int wid = tid >> 5;
    const int lane = tid & 31;
    const int wr = wid >> 2;
    const int wc = wid & 3;
    const int g = lane >> 2;
    const int tig = lane & 3;

    const int z = blockIdx.z;
    const long offA = (long)(z / divA) * sA1 + (long)(z % divA) * sA2;
    const long offB = (long)(z / divB) * sB1 + (long)(z % divB) * sB2;
    Ahi += offA; Alo += offA; Bhi += offB; Blo += offB;
    C += (long)(z / divC) * sC1 + (long)(z % divC) * sC2;
    if (EPI == 2) AUX += (long)z * sAux;
    const int rowBase = blockIdx.y * 128;
    const int colBase = blockIdx.x * 128;

    // staging constants
    const int nr = tid >> 1, nh = tid & 1;                 // normal: row, 16B-half
    const uint32_t ndst = (uint32_t)(nr * 32 + 16 * (nh ^ ((nr >> 2) & 1)));
    const int tkr = tid >> 4, tnb = tid & 15;              // trans: k-row, n-block
    const uint32_t tdst = (uint32_t)(tkr * 256 + 16 * ((tnb ^ (tkr & 7)) & 15));

    float acc[4][4][4];
    #pragma unroll
    for (int i = 0; i < 4; i++)
        #pragma unroll
        for (int j = 0; j < 4; j++)
            #pragma unroll
            for (int k = 0; k < 4; k++) acc[i][j][k] = 0.0f;

    const int nStages = K >> 5;

    auto stage = [&](int buf, int c) {
        const int k0 = c << 5;
        #pragma unroll
        for (int sub = 0; sub < 2; sub++) {
            // A tiles
            if (!ATR) {
                long src = (long)(rowBase + nr) * lda + k0 + sub * 16 + 8 * nh;
                cp16(tile_addr(sb, buf, 0, sub, 0) + ndst, Ahi + src);
                cp16(tile_addr(sb, buf, 0, sub, 1) + ndst, Alo + src);
            } else {
                long src = (long)(k0 + sub * 16 + tkr) * lda + rowBase + 8 * tnb;
                cp16(tile_addr(sb, buf, 0, sub, 0) + tdst, Ahi + src);
                cp16(tile_addr(sb, buf, 0, sub, 1) + tdst, Alo + src);
            }
            // B tiles
            if (!BTR) {
                long src = (long)(colBase + nr) * ldb + k0 + sub * 16 + 8 * nh;
                cp16(tile_addr(sb, buf, 1, sub, 0) + ndst, Bhi + src);
                cp16(tile_addr(sb, buf, 1, sub, 1) + ndst, Blo + src);
            } else {
                long src = (long)(k0 + sub * 16 + tkr) * ldb + colBase + 8 * tnb;
                cp16(tile_addr(sb, buf, 1, sub, 0) + tdst, Bhi + src);
                cp16(tile_addr(sb, buf, 1, sub, 1) + tdst, Blo + src);
            }
        }
    };

    auto compute = [&](int buf) {
        #pragma unroll
        for (int sub = 0; sub < 2; sub++) {
            uint32_t afr[2][4][4], bfr[2][4][2];
            // ---- A fragments ----
            #pragma unroll
            for (int hl = 0; hl < 2; hl++) {
                const uint32_t tb = tile_addr(sb, buf, 0, sub, hl);
                if (!ATR) {
                    const int rl = (lane & 7) + 8 * ((lane >> 3) & 1);
                    const int h = lane >> 4;
                    const uint32_t lo32 = (uint32_t)(rl * 32 + 16 * (h ^ ((rl >> 2) & 1)));
                    #pragma unroll
                    for (int ms = 0; ms < 4; ms++)
                        ldsm_x4(&afr[hl][ms][0], tb + (uint32_t)((wr * 64 + ms * 16) * 32) + lo32);
                } else {
                    const int kr = (lane & 7) + 8 * (lane >> 4);
                    const int mb0 = wr * 8 + ((lane >> 3) & 1);
                    #pragma unroll
                    for (int ms = 0; ms < 4; ms++) {
                        const int mb = mb0 + ms * 2;
                        ldsm_x4_t(&afr[hl][ms][0],
                                  tb + (uint32_t)(kr * 256 + 16 * ((mb ^ (kr & 7)) & 15)));
                    }
                }
            }
            // ---- B fragments ----
            #pragma unroll
            for (int hl = 0; hl < 2; hl++) {
                const uint32_t tb = tile_addr(sb, buf, 1, sub, hl);
                if (!BTR) {
                    const int rl = (lane >> 4) * 8 + (lane & 7);
                    const int h = (lane >> 3) & 1;
                    const uint32_t lo32 = (uint32_t)(rl * 32 + 16 * (h ^ ((rl >> 2) & 1)));
                    #pragma unroll
                    for (int p = 0; p < 2; p++) {
                        uint32_t r4[4];
                        ldsm_x4(r4, tb + (uint32_t)((wc * 32 + p * 16) * 32) + lo32);
                        bfr[hl][2 * p][0] = r4[0]; bfr[hl][2 * p][1] = r4[1];
                        bfr[hl][2 * p + 1][0] = r4[2]; bfr[hl][2 * p + 1][1] = r4[3];
                    }
                } else {
                    const int kr = (lane & 7) + 8 * ((lane >> 3) & 1);
                    const int nb0 = wc * 4 + (lane >> 4);
                    #pragma unroll
                    for (int p = 0; p < 2; p++) {
                        const int nb = nb0 + p * 2;
                        uint32_t r4[4];
                        ldsm_x4_t(r4, tb + (uint32_t)(kr * 256 + 16 * ((nb ^ (kr & 7)) & 15)));
                        bfr[hl][2 * p][0] = r4[0]; bfr[hl][2 * p][1] = r4[1];
                        bfr[hl][2 * p + 1][0] = r4[2]; bfr[hl][2 * p + 1][1] = r4[3];
                    }
                }
            }
            // ---- 3-term MMAs (term-major for independent chains) ----
            #pragma unroll
            for (int ms = 0; ms < 4; ms++)
                #pragma unroll
                for (int ns = 0; ns < 4; ns++)
                    mma_bf16(acc[ms][ns], afr[0][ms], bfr[0][ns]);
            #pragma unroll
            for (int ms = 0; ms < 4; ms++)
                #pragma unroll
                for (int ns = 0; ns < 4; ns++)
                    mma_bf16(acc[ms][ns], afr[0][ms], bfr[1][ns]);
            #pragma unroll
            for (int ms = 0; ms < 4; ms++)
                #pragma unroll
                for (int ns = 0; ns < 4; ns++)
                    mma_bf16(acc[ms][ns], afr[1][ms], bfr[0][ns]);
        }
    };

    stage(0, 0);
    CP_COMMIT();
    for (int c = 0; c < nStages; c++) {
        if (c + 1 < nStages) { stage((c + 1) & 1, c + 1); CP_COMMIT(); CP_WAIT1(); }
        else { CP_WAIT0(); }
        __syncthreads();
        compute(c & 1);
        __syncthreads();
    }

    // Epilogue: m16n8k16 C layout: c0/c1 -> (row g, cols 2tig..+1), c2/c3 -> row g+8.
    #pragma unroll
    for (int ms = 0; ms < 4; ms++) {
        const int r = rowBase + wr * 64 + ms * 16 + g;
        #pragma unroll
        for (int ns = 0; ns < 4; ns++) {
            const int col = colBase + wc * 32 + ns * 8 + tig * 2;
            float2 v0 = make_float2(acc[ms][ns][0], acc[ms][ns][1]);
            float2 v1 = make_float2(acc[ms][ns][2], acc[ms][ns][3]);
            if (EPI >= 1) {
                v0.x = fmaxf(v0.x, 0.0f); v0.y = fmaxf(v0.y, 0.0f);
                v1.x = fmaxf(v1.x, 0.0f); v1.y = fmaxf(v1.y, 0.0f);
            }
            if (EPI == 2) {
                float2 a0 = *(const float2*)(AUX + (long)r * ldaux + col);
                float2 a1 = *(const float2*)(AUX + (long)(r + 8) * ldaux + col);
                v0.x *= a0.x; v0.y *= a0.y;
                v1.x *= a1.x; v1.y *= a1.y;
            }
            *(float2*)(C + (long)r * ldc + col) = v0;
            *(float2*)(C + (long)(r + 8) * ldc + col) = v1;
        }
    }
}

// ---------------------------------------------------------------------------
// Split: fp32 -> bf16 hi + bf16 lo (lo = bf16(x - hi))
// ---------------------------------------------------------------------------
__global__ void split_kernel(const float* __restrict__ in,
                             __nv_bfloat16* __restrict__ hi,
                             __nv_bfloat16* __restrict__ lo) {
    long i = ((long)blockIdx.x * blockDim.x + threadIdx.x) * 4;
    float4 v = *(const float4*)(in + i);
    __nv_bfloat16 h0 = __float2bfloat16(v.x);
    __nv_bfloat16 h1 = __float2bfloat16(v.y);
    __nv_bfloat16 h2 = __float2bfloat16(v.z);
    __nv_bfloat16 h3 = __float2bfloat16(v.w);
    __nv_bfloat16 l0 = __float2bfloat16(v.x - __bfloat162float(h0));
    __nv_bfloat16 l1 = __float2bfloat16(v.y - __bfloat162float(h1));
    __nv_bfloat16 l2 = __float2bfloat16(v.z - __bfloat162float(h2));
    __nv_bfloat16 l3 = __float2bfloat16(v.w - __bfloat162float(h3));
    __nv_bfloat162* hp = (__nv_bfloat162*)(hi + i);
    __nv_bfloat162* lp = (__nv_bfloat162*)(lo + i);
    hp[0] = __halves2bfloat162(h0, h1);
    hp[1] = __halves2bfloat162(h2, h3);
    lp[0] = __halves2bfloat162(l0, l1);
    lp[1] = __halves2bfloat162(l2, l3);
}

// ---------------------------------------------------------------------------
// Elementwise kernels
// ---------------------------------------------------------------------------
__device__ __forceinline__ float block_sum_256(float v, float* smem) {
    #pragma unroll
    for (int o = 16; o > 0; o >>= 1) v += __shfl_down_sync(0xffffffffu, v, o);
    int w = threadIdx.x >> 5, l = threadIdx.x & 31;
    if (l == 0) smem[w] = v;
    __syncthreads();
    if (w == 0) {
        float s = (l < 8) ? smem[l] : 0.0f;
        #pragma unroll
        for (int o = 4; o > 0; o >>= 1) s += __shfl_down_sync(0xffffffffu, s, o);
        if (l == 0) smem[0] = s;
    }
    __syncthreads();
    float r = smem[0];
    __syncthreads();
    return r;
}

__global__ void rope_tables_kernel(float* cosT, float* sinT) {
    int t = blockIdx.x;
    int j = threadIdx.x;
    double expnt = (2.0 * (double)j) / (double)DH;
    double inv = pow(10000.0, -expnt);
    double phase = (double)t * inv;
    float c = (float)cos(phase);
    float s = (float)sin(phase);
    cosT[t * DH + j] = c;  cosT[t * DH + 512 + j] = c;
    sinT[t * DH + j] = s;  sinT[t * DH + 512 + j] = s;
}

__global__ void embed_ln_kernel(const int* __restrict__ tokens,
                                const float* __restrict__ emb_w,
                                float* __restrict__ v) {
    __shared__ float smem[8];
    int bt = blockIdx.x;
    int d = threadIdx.x;
    int tok = tokens[bt];
    float val = emb_w[tok * DD + d];
    float m = block_sum_256(val, smem) * (1.0f / DD);
    float c = val - m;
    float var = block_sum_256(c * c, smem) * (1.0f / DD);
    v[bt * DD + d] = c * rsqrtf(var + EPS);
}

__global__ void rope_apply_kernel(const float* __restrict__ x,
                                  const float* __restrict__ cosT,
                                  const float* __restrict__ sinT,
                                  float* __restrict__ xr) {
    long idx = (long)blockIdx.x * blockDim.x + threadIdx.x;
    int e = (int)(idx & (DH - 1));
    int t = (int)((idx >> 10) & (TT - 1));
    float xv = x[idx];
    float other = (e < 512) ? -x[idx + 512] : x[idx - 512];
    xr[idx] = xv * cosT[t * DH + e] + other * sinT[t * DH + e];
}

// v = LN(v + LN(z0+z1+z2+z3))
__global__ void fuse_ln4_kernel(const float* __restrict__ z,
                                float* __restrict__ v) {
    __shared__ float smem[8];
    int bt = blockIdx.x;
    int d = threadIdx.x;
    long i = (long)bt * DD + d;
    const long S = (long)BB * TT * DD;
    float u = z[i] + z[i + S] + z[i + 2 * S] + z[i + 3 * S];
    float m1 = block_sum_256(u, smem) * (1.0f / DD);
    float c1 = u - m1;
    float var1 = block_sum_256(c1 * c1, smem) * (1.0f / DD);
    float lnz = c1 * rsqrtf(var1 + EPS);
    float w = v[i] + lnz;
    float m2 = block_sum_256(w, smem) * (1.0f / DD);
    float c2 = w - m2;
    float var2 = block_sum_256(c2 * c2, smem) * (1.0f / DD);
    v[i] = c2 * rsqrtf(var2 + EPS);
}

// ---------------------------------------------------------------------------
// Host launcher
// ---------------------------------------------------------------------------
#define SMEM_SZ (16 * TILE_B)

template <int EPI, bool ATR, bool BTR>
static void set_attr() {
    cudaFuncSetAttribute(mm_bf16x3_kernel<EPI, ATR, BTR>,
                         cudaFuncAttributeMaxDynamicSharedMemorySize, SMEM_SZ);
}

extern "C" void kernel_launch(void* const* d_in, const int* in_sizes, int n_in,
                              void* d_out, int out_size) {
    const int*   tokens  = (const int*)d_in[0];
    const float* emb_w   = (const float*)d_in[1];
    const float* E       = (const float*)d_in[2];
    const float* Dx      = (const float*)d_in[3];
    const float* Dy      = (const float*)d_in[4];
    const float* readout = (const float*)d_in[5];
    float* out = (float*)d_out;

    float *v, *x, *xr, *w2, *a, *ye, *zb, *cosT, *sinT;
    cudaGetSymbolAddress((void**)&v, g_v);
    cudaGetSymbolAddress((void**)&x, g_x);
    cudaGetSymbolAddress((void**)&xr, g_xr);
    cudaGetSymbolAddress((void**)&w2, g_w2);
    cudaGetSymbolAddress((void**)&a, g_a);
    cudaGetSymbolAddress((void**)&ye, g_ye);
    cudaGetSymbolAddress((void**)&zb, g_z);
    cudaGetSymbolAddress((void**)&cosT, g_cos);
    cudaGetSymbolAddress((void**)&sinT, g_sin);

    __nv_bfloat16 *vh, *vl, *xrh, *xrl, *w2h, *w2l, *ah, *al, *yeh, *yel;
    __nv_bfloat16 *dxh, *dxl, *dyh, *dyl, *eh, *el, *roh, *rol;
    cudaGetSymbolAddress((void**)&vh, s_v_hi);   cudaGetSymbolAddress((void**)&vl, s_v_lo);
    cudaGetSymbolAddress((void**)&xrh, s_xr_hi); cudaGetSymbolAddress((void**)&xrl, s_xr_lo);
    cudaGetSymbolAddress((void**)&w2h, s_w2_hi); cudaGetSymbolAddress((void**)&w2l, s_w2_lo);
    cudaGetSymbolAddress((void**)&ah, s_a_hi);   cudaGetSymbolAddress((void**)&al, s_a_lo);
    cudaGetSymbolAddress((void**)&yeh, s_ye_hi); cudaGetSymbolAddress((void**)&yel, s_ye_lo);
    cudaGetSymbolAddress((void**)&dxh, s_dx_hi); cudaGetSymbolAddress((void**)&dxl, s_dx_lo);
    cudaGetSymbolAddress((void**)&dyh, s_dy_hi); cudaGetSymbolAddress((void**)&dyl, s_dy_lo);
    cudaGetSymbolAddress((void**)&eh, s_e_hi);   cudaGetSymbolAddress((void**)&el, s_e_lo);
    cudaGetSymbolAddress((void**)&roh, s_ro_hi); cudaGetSymbolAddress((void**)&rol, s_ro_lo);

    set_attr<1, false, true>();
    set_attr<0, true, true>();
    set_attr<0, false, false>();
    set_attr<2, false, true>();
    set_attr<0, false, true>();

    rope_tables_kernel<<<TT, 512>>>(cosT, sinT);
    embed_ln_kernel<<<BB * TT, 256>>>(tokens, emb_w, v);

    // Weight splits (inputs are const fp32)
    split_kernel<<<(HH * DD * DH) / 1024, 256>>>(Dx, dxh, dxl);
    split_kernel<<<(HH * DD * DH) / 1024, 256>>>(Dy, dyh, dyl);
    split_kernel<<<(NN_ * DD) / 1024, 256>>>(E, eh, el);
    split_kernel<<<(DD * VV) / 1024, 256>>>(readout, roh, rol);
    split_kernel<<<(BB * TT * DD) / 1024, 256>>>(v, vh, vl);

    const long TDh = (long)TT * DH;
    const long TD  = (long)TT * DD;
    const long DDh = (long)DD * DH;
    const long TN  = (long)TT * NN_;

    for (int l = 0; l < LL; l++) {
        // 1) x = relu(v @ Dx_h): M=T N=Dh K=D. A=v [M,K]; B=Dx_h [K,N] (BTR).
        mm_bf16x3_kernel<1, false, true><<<dim3(8, 8, BB * HH), 256, SMEM_SZ>>>(
            vh, vl, dxh, dxl, x, nullptr,
            DD, DD, DH, DH, 0,
            HH, TD, 0,   HH, 0, DDh,   1, TDh, 0,   0);

        // 2) RoPE + split xr
        rope_apply_kernel<<<(BB * HH * TT * DH) / 256, 256>>>(x, cosT, sinT, xr);
        split_kernel<<<(BB * HH * TT * DH) / 1024, 256>>>(xr, xrh, xrl);

        // 3) w2[d,e] = sum_t v[t,d] xr[t,e]: M=D N=Dh K=T. A=v [K,M] (ATR); B=xr [K,N] (BTR).
        mm_bf16x3_kernel<0, true, true><<<dim3(8, 2, BB * HH), 256, SMEM_SZ>>>(
            vh, vl, xrh, xrl, w2, nullptr,
            TT, DD, DH, DH, 0,
            HH, TD, 0,   1, TDh, 0,   1, DDh, 0,   0);
        split_kernel<<<(BB * HH * DD * DH) / 1024, 256>>>(w2, w2h, w2l);

        // 4) a[t,d] = sum_e xr[t,e] w2[d,e]: M=T N=D K=Dh. A=xr [M,K]; B=w2 [N,K].
        mm_bf16x3_kernel<0, false, false><<<dim3(2, 8, BB * HH), 256, SMEM_SZ>>>(
            xrh, xrl, w2h, w2l, a, nullptr,
            DH, DH, DH, DD, 0,
            1, TDh, 0,   1, DDh, 0,   1, TD, 0,   0);
        split_kernel<<<(BB * HH * TT * DD) / 1024, 256>>>(a, ah, al);

        // 5) ye = relu(a @ Dy_h) * x: M=T N=Dh K=D. A=a; B=Dy_h [K,N] (BTR); AUX=x.
        mm_bf16x3_kernel<2, false, true><<<dim3(8, 8, BB * HH), 256, SMEM_SZ>>>(
            ah, al, dyh, dyl, ye, x,
            DD, DD, DH, NN_, DH,
            1, TD, 0,   HH, 0, DDh,   HH, TN, DH,   TDh);
        split_kernel<<<(BB * TT * NN_) / 1024, 256>>>(ye, yeh, yel);

        // 6) z partials (split-K x4): M=B*T N=D K=4096/4. A=ye; B=E [K,N] (BTR).
        mm_bf16x3_kernel<0, false, true><<<dim3(2, 32, 4), 256, SMEM_SZ>>>(
            yeh, yel, eh, el, zb, nullptr,
            NN_ / 4, NN_, DD, DD, 0,
            1, NN_ / 4, 0,   1, (long)(NN_ / 4) * DD, 0,   1, (long)BB * TT * DD, 0,   0);

        // 7) v = LN(v + LN(sum z)); split v for next layer / readout
        fuse_ln4_kernel<<<BB * TT, 256>>>(zb, v);
        split_kernel<<<(BB * TT * DD) / 1024, 256>>>(v, vh, vl);
    }

    // out = v @ readout: M=B*T N=V K=D. A=v; B=readout [K,N] (BTR).
    mm_bf16x3_kernel<0, false, true><<<dim3(2, 32, 1), 256, SMEM_SZ>>>(
        vh, vl, roh, rol, out, nullptr,
        DD, DD, VV, VV, 0,
        1, 0, 0,   1, 0, 0,   1, 0, 0,   0);
}

// round 7
// speedup vs baseline: 4.3143x; 1.1248x over previous
#include <cuda_runtime.h>
#include <cuda_bf16.h>
#include <math.h>
#include <stdint.h>

// Problem constants
#define BB 4
#define TT 1024
#define HH 4
#define NN_ 4096
#define DD 256
#define DH 1024
#define LL 6
#define VV 256
#define EPS 1e-5f

// ---------------------------------------------------------------------------
// Scratch buffers (device globals; no allocation allowed)
// ---------------------------------------------------------------------------
__device__ float g_v[BB * TT * DD];
__device__ float g_x[BB * HH * TT * DH];
__device__ float g_z[4 * BB * TT * DD];     // split-K partials
__device__ float g_cos[TT * DH];
__device__ float g_sin[TT * DH];

// bf16 hi/lo split operand buffers
__device__ __nv_bfloat16 s_v_hi[BB * TT * DD],   s_v_lo[BB * TT * DD];
__device__ __nv_bfloat16 s_xr_hi[BB * HH * TT * DH], s_xr_lo[BB * HH * TT * DH];
__device__ __nv_bfloat16 s_w2_hi[BB * HH * DD * DH], s_w2_lo[BB * HH * DD * DH];
__device__ __nv_bfloat16 s_a_hi[BB * HH * TT * DD],  s_a_lo[BB * HH * TT * DD];
__device__ __nv_bfloat16 s_ye_hi[BB * TT * NN_], s_ye_lo[BB * TT * NN_];
__device__ __nv_bfloat16 s_dx_hi[HH * DD * DH],  s_dx_lo[HH * DD * DH];
__device__ __nv_bfloat16 s_dy_hi[HH * DD * DH],  s_dy_lo[HH * DD * DH];
__device__ __nv_bfloat16 s_e_hi[NN_ * DD],       s_e_lo[NN_ * DD];
__device__ __nv_bfloat16 s_ro_hi[DD * VV],       s_ro_lo[DD * VV];

// ---------------------------------------------------------------------------
// PTX helpers
// ---------------------------------------------------------------------------
__device__ __forceinline__ uint32_t smem_to_u32(const void* p) {
    uint32_t a;
    asm("{ .reg .u64 t; cvta.to.shared.u64 t, %1; cvt.u32.u64 %0, t; }" : "=r"(a) : "l"(p));
    return a;
}
__device__ __forceinline__ void cp16(uint32_t dst, const void* src) {
    asm volatile("cp.async.cg.shared.global [%0], [%1], 16;" :: "r"(dst), "l"(src));
}
#define CP_COMMIT() asm volatile("cp.async.commit_group;" ::: "memory")
#define CP_WAIT0() asm volatile("cp.async.wait_group 0;" ::: "memory")
#define CP_WAIT1() asm volatile("cp.async.wait_group 1;" ::: "memory")

__device__ __forceinline__ void ldsm_x4(uint32_t* r, uint32_t addr) {
    asm volatile("ldmatrix.sync.aligned.m8n8.x4.shared.b16 {%0,%1,%2,%3}, [%4];"
                 : "=r"(r[0]), "=r"(r[1]), "=r"(r[2]), "=r"(r[3]) : "r"(addr));
}
__device__ __forceinline__ void ldsm_x4_t(uint32_t* r, uint32_t addr) {
    asm volatile("ldmatrix.sync.aligned.m8n8.x4.trans.shared.b16 {%0,%1,%2,%3}, [%4];"
                 : "=r"(r[0]), "=r"(r[1]), "=r"(r[2]), "=r"(r[3]) : "r"(addr));
}
__device__ __forceinline__ void mma_bf16(float* d, const uint32_t* a, const uint32_t* b) {
    asm volatile(
        "mma.sync.aligned.m16n8k16.row.col.f32.bf16.bf16.f32 "
        "{%0,%1,%2,%3}, {%4,%5,%6,%7}, {%8,%9}, {%0,%1,%2,%3};"
        : "+f"(d[0]), "+f"(d[1]), "+f"(d[2]), "+f"(d[3])
        : "r"(a[0]), "r"(a[1]), "r"(a[2]), "r"(a[3]), "r"(b[0]), "r"(b[1]));
}
__device__ __forceinline__ __nv_bfloat162 split2(float x, float y,
                                                 __nv_bfloat162* lo) {
    __nv_bfloat16 hx = __float2bfloat16(x);
    __nv_bfloat16 hy = __float2bfloat16(y);
    *lo = __halves2bfloat162(__float2bfloat16(x - __bfloat162float(hx)),
                             __float2bfloat16(y - __bfloat162float(hy)));
    return __halves2bfloat162(hx, hy);
}

// ---------------------------------------------------------------------------
// bf16x3 GEMM: C = epi(A @ B^T), 128x128 CTA tile, 8 warps (2x4), K-stage 32.
//   A arrays: ATR=false -> [M,K]; ATR=true -> [K,M].
//   B arrays: BTR=false -> [N,K]; BTR=true -> [K,N].
//   EPI 0: acc; 1: relu; 2: relu*AUX.
//   OUTSPLIT: write bf16 hi/lo pair (Chi/Clo) instead of fp32 C.
// ---------------------------------------------------------------------------
#define TILE_B 4096
__device__ __forceinline__ uint32_t tile_addr(uint32_t sb, int buf, int ab, int sub, int hl) {
    return sb + (uint32_t)((((buf * 2 + ab) * 2 + sub) * 2 + hl) * TILE_B);
}

template <int EPI, bool ATR, bool BTR, bool OUTSPLIT>
__global__ void __launch_bounds__(256)
mm_bf16x3_kernel(const __nv_bfloat16* __restrict__ Ahi, const __nv_bfloat16* __restrict__ Alo,
                 const __nv_bfloat16* __restrict__ Bhi, const __nv_bfloat16* __restrict__ Blo,
                 float* __restrict__ C,
                 __nv_bfloat16* __restrict__ Chi, __nv_bfloat16* __restrict__ Clo,
                 const float* __restrict__ AUX,
                 int K, int lda, int ldb, int ldc, int ldaux,
                 int divA, long sA1, long sA2,
                 int divB, long sB1, long sB2,
                 int divC, long sC1, long sC2,
                 long sAux) {
    extern __shared__ char smem[];
    const uint32_t sb = smem_to_u32(smem);
    const int tid = threadIdx.x;
    const int wid = tid >> 5;
    const int lane = tid & 31;
    const int wr = wid >> 2;
    const int wc = wid & 3;
    const int g = lane >> 2;
    const int tig = lane & 3;

    const int z = blockIdx.z;
    const long offA = (long)(z / divA) * sA1 + (long)(z % divA) * sA2;
    const long offB = (long)(z / divB) * sB1 + (long)(z % divB) * sB2;
    const long offC = (long)(z / divC) * sC1 + (long)(z % divC) * sC2;
    Ahi += offA; Alo += offA; Bhi += offB; Blo += offB;
    if (!OUTSPLIT) C += offC; else { Chi += offC; Clo += offC; }
    if (EPI == 2) AUX += (long)z * sAux;
    const int rowBase = blockIdx.y * 128;
    const int colBase = blockIdx.x * 128;

    // staging constants
    const int nr = tid >> 1, nh = tid & 1;                 // normal: row, 16B-half
    const uint32_t ndst = (uint32_t)(nr * 32 + 16 * (nh ^ ((nr >> 2) & 1)));
    const int tkr = tid >> 4, tnb = tid & 15;              // trans: k-row, n-block
    const uint32_t tdst = (uint32_t)(tkr * 256 + 16 * ((tnb ^ (tkr & 7)) & 15));

    float acc[4][4][4];
    #pragma unroll
    for (int i = 0; i < 4; i++)
        #pragma unroll
        for (int j = 0; j < 4; j++)
            #pragma unroll
            for (int k = 0; k < 4; k++) acc[i][j][k] = 0.0f;

    const int nStages = K >> 5;

    auto stage = [&](int buf, int c) {
        const int k0 = c << 5;
        #pragma unroll
        for (int sub = 0; sub < 2; sub++) {
            if (!ATR) {
                long src = (long)(rowBase + nr) * lda + k0 + sub * 16 + 8 * nh;
                cp16(tile_addr(sb, buf, 0, sub, 0) + ndst, Ahi + src);
                cp16(tile_addr(sb, buf, 0, sub, 1) + ndst, Alo + src);
            } else {
                long src = (long)(k0 + sub * 16 + tkr) * lda + rowBase + 8 * tnb;
                cp16(tile_addr(sb, buf, 0, sub, 0) + tdst, Ahi + src);
                cp16(tile_addr(sb, buf, 0, sub, 1) + tdst, Alo + src);
            }
            if (!BTR) {
                long src = (long)(colBase + nr) * ldb + k0 + sub * 16 + 8 * nh;
                cp16(tile_addr(sb, buf, 1, sub, 0) + ndst, Bhi + src);
                cp16(tile_addr(sb, buf, 1, sub, 1) + ndst, Blo + src);
            } else {
                long src = (long)(k0 + sub * 16 + tkr) * ldb + colBase + 8 * tnb;
                cp16(tile_addr(sb, buf, 1, sub, 0) + tdst, Bhi + src);
                cp16(tile_addr(sb, buf, 1, sub, 1) + tdst, Blo + src);
            }
        }
    };

    auto compute = [&](int buf) {
        #pragma unroll
        for (int sub = 0; sub < 2; sub++) {
            uint32_t afr[2][4][4], bfr[2][4][2];
            #pragma unroll
            for (int hl = 0; hl < 2; hl++) {
                const uint32_t tb = tile_addr(sb, buf, 0, sub, hl);
                if (!ATR) {
                    const int rl = (lane & 7) + 8 * ((lane >> 3) & 1);
                    const int h = lane >> 4;
                    const uint32_t lo32 = (uint32_t)(rl * 32 + 16 * (h ^ ((rl >> 2) & 1)));
                    #pragma unroll
                    for (int ms = 0; ms < 4; ms++)
                        ldsm_x4(&afr[hl][ms][0], tb + (uint32_t)((wr * 64 + ms * 16) * 32) + lo32);
                } else {
                    const int kr = (lane & 7) + 8 * (lane >> 4);
                    const int mb0 = wr * 8 + ((lane >> 3) & 1);
                    #pragma unroll
                    for (int ms = 0; ms < 4; ms++) {
                        const int mb = mb0 + ms * 2;
                        ldsm_x4_t(&afr[hl][ms][0],
                                  tb + (uint32_t)(kr * 256 + 16 * ((mb ^ (kr & 7)) & 15)));
                    }
                }
            }
            #pragma unroll
            for (int hl = 0; hl < 2; hl++) {
                const uint32_t tb = tile_addr(sb, buf, 1, sub, hl);
                if (!BTR) {
                    const int rl = (lane >> 4) * 8 + (lane & 7);
                    const int h = (lane >> 3) & 1;
                    const uint32_t lo32 = (uint32_t)(rl * 32 + 16 * (h ^ ((rl >> 2) & 1)));
                    #pragma unroll
                    for (int p = 0; p < 2; p++) {
                        uint32_t r4[4];
                        ldsm_x4(r4, tb + (uint32_t)((wc * 32 + p * 16) * 32) + lo32);
                        bfr[hl][2 * p][0] = r4[0]; bfr[hl][2 * p][1] = r4[1];
                        bfr[hl][2 * p + 1][0] = r4[2]; bfr[hl][2 * p + 1][1] = r4[3];
                    }
                } else {
                    const int kr = (lane & 7) + 8 * ((lane >> 3) & 1);
                    const int nb0 = wc * 4 + (lane >> 4);
                    #pragma unroll
                    for (int p = 0; p < 2; p++) {
                        const int nb = nb0 + p * 2;
                        uint32_t r4[4];
                        ldsm_x4_t(r4, tb + (uint32_t)(kr * 256 + 16 * ((nb ^ (kr & 7)) & 15)));
                        bfr[hl][2 * p][0] = r4[0]; bfr[hl][2 * p][1] = r4[1];
                        bfr[hl][2 * p + 1][0] = r4[2]; bfr[hl][2 * p + 1][1] = r4[3];
                    }
                }
            }
            #pragma unroll
            for (int ms = 0; ms < 4; ms++)
                #pragma unroll
                for (int ns = 0; ns < 4; ns++)
                    mma_bf16(acc[ms][ns], afr[0][ms], bfr[0][ns]);
            #pragma unroll
            for (int ms = 0; ms < 4; ms++)
                #pragma unroll
                for (int ns = 0; ns < 4; ns++)
                    mma_bf16(acc[ms][ns], afr[0][ms], bfr[1][ns]);
            #pragma unroll
            for (int ms = 0; ms < 4; ms++)
                #pragma unroll
                for (int ns = 0; ns < 4; ns++)
                    mma_bf16(acc[ms][ns], afr[1][ms], bfr[0][ns]);
        }
    };

    stage(0, 0);
    CP_COMMIT();
    for (int c = 0; c < nStages; c++) {
        if (c + 1 < nStages) { stage((c + 1) & 1, c + 1); CP_COMMIT(); CP_WAIT1(); }
        else { CP_WAIT0(); }
        __syncthreads();
        compute(c & 1);
        __syncthreads();
    }

    // Epilogue
    #pragma unroll
    for (int ms = 0; ms < 4; ms++) {
        const int r = rowBase + wr * 64 + ms * 16 + g;
        #pragma unroll
        for (int ns = 0; ns < 4; ns++) {
            const int col = colBase + wc * 32 + ns * 8 + tig * 2;
            float2 v0 = make_float2(acc[ms][ns][0], acc[ms][ns][1]);
            float2 v1 = make_float2(acc[ms][ns][2], acc[ms][ns][3]);
            if (EPI >= 1) {
                v0.x = fmaxf(v0.x, 0.0f); v0.y = fmaxf(v0.y, 0.0f);
                v1.x = fmaxf(v1.x, 0.0f); v1.y = fmaxf(v1.y, 0.0f);
            }
            if (EPI == 2) {
                float2 a0 = *(const float2*)(AUX + (long)r * ldaux + col);
                float2 a1 = *(const float2*)(AUX + (long)(r + 8) * ldaux + col);
                v0.x *= a0.x; v0.y *= a0.y;
                v1.x *= a1.x; v1.y *= a1.y;
            }
            if (!OUTSPLIT) {
                *(float2*)(C + (long)r * ldc + col) = v0;
                *(float2*)(C + (long)(r + 8) * ldc + col) = v1;
            } else {
                __nv_bfloat162 lo0, lo1;
                __nv_bfloat162 hi0 = split2(v0.x, v0.y, &lo0);
                __nv_bfloat162 hi1 = split2(v1.x, v1.y, &lo1);
                *(__nv_bfloat162*)(Chi + (long)r * ldc + col) = hi0;
                *(__nv_bfloat162*)(Clo + (long)r * ldc + col) = lo0;
                *(__nv_bfloat162*)(Chi + (long)(r + 8) * ldc + col) = hi1;
                *(__nv_bfloat162*)(Clo + (long)(r + 8) * ldc + col) = lo1;
            }
        }
    }
}

// ---------------------------------------------------------------------------
// Split: fp32 -> bf16 hi + bf16 lo (weights, once per launch)
// ---------------------------------------------------------------------------
__global__ void split_kernel(const float* __restrict__ in,
                             __nv_bfloat16* __restrict__ hi,
                             __nv_bfloat16* __restrict__ lo) {
    long i = ((long)blockIdx.x * blockDim.x + threadIdx.x) * 4;
    float4 v = *(const float4*)(in + i);
    __nv_bfloat162 l0, l1;
    __nv_bfloat162 h0 = split2(v.x, v.y, &l0);
    __nv_bfloat162 h1 = split2(v.z, v.w, &l1);
    __nv_bfloat162* hp = (__nv_bfloat162*)(hi + i);
    __nv_bfloat162* lp = (__nv_bfloat162*)(lo + i);
    hp[0] = h0; hp[1] = h1;
    lp[0] = l0; lp[1] = l1;
}

// ---------------------------------------------------------------------------
// Elementwise kernels
// ---------------------------------------------------------------------------
__device__ __forceinline__ float block_sum_256(float v, float* smem) {
    #pragma unroll
    for (int o = 16; o > 0; o >>= 1) v += __shfl_down_sync(0xffffffffu, v, o);
    int w = threadIdx.x >> 5, l = threadIdx.x & 31;
    if (l == 0) smem[w] = v;
    __syncthreads();
    if (w == 0) {
        float s = (l < 8) ? smem[l] : 0.0f;
        #pragma unroll
        for (int o = 4; o > 0; o >>= 1) s += __shfl_down_sync(0xffffffffu, s, o);
        if (l == 0) smem[0] = s;
    }
    __syncthreads();
    float r = smem[0];
    __syncthreads();
    return r;
}

__global__ void rope_tables_kernel(float* cosT, float* sinT) {
    int t = blockIdx.x;
    int j = threadIdx.x;
    double expnt = (2.0 * (double)j) / (double)DH;
    double inv = pow(10000.0, -expnt);
    double phase = (double)t * inv;
    float c = (float)cos(phase);
    float s = (float)sin(phase);
    cosT[t * DH + j] = c;  cosT[t * DH + 512 + j] = c;
    sinT[t * DH + j] = s;  sinT[t * DH + 512 + j] = s;
}

__global__ void embed_ln_kernel(const int* __restrict__ tokens,
                                const float* __restrict__ emb_w,
                                float* __restrict__ v,
                                __nv_bfloat16* __restrict__ vh,
                                __nv_bfloat16* __restrict__ vl) {
    __shared__ float smem[8];
    int bt = blockIdx.x;
    int d = threadIdx.x;
    int tok = tokens[bt];
    float val = emb_w[tok * DD + d];
    float m = block_sum_256(val, smem) * (1.0f / DD);
    float c = val - m;
    float var = block_sum_256(c * c, smem) * (1.0f / DD);
    float r = c * rsqrtf(var + EPS);
    v[bt * DD + d] = r;
    __nv_bfloat16 h = __float2bfloat16(r);
    vh[bt * DD + d] = h;
    vl[bt * DD + d] = __float2bfloat16(r - __bfloat162float(h));
}

// RoPE fused with split: reads x fp32, writes xr hi/lo bf16 directly.
// Each thread handles 2 consecutive elements (same rotate-half side).
__global__ void rope_split_kernel(const float* __restrict__ x,
                                  const float* __restrict__ cosT,
                                  const float* __restrict__ sinT,
                                  __nv_bfloat16* __restrict__ xrh,
                                  __nv_bfloat16* __restrict__ xrl) {
    long idx = ((long)blockIdx.x * blockDim.x + threadIdx.x) * 2;
    int e = (int)(idx & (DH - 1));
    int t = (int)((idx >> 10) & (TT - 1));
    float2 xv = *(const float2*)(x + idx);
    float2 ov;
    if (e < 512) {
        ov = *(const float2*)(x + idx + 512);
        ov.x = -ov.x; ov.y = -ov.y;
    } else {
        ov = *(const float2*)(x + idx - 512);
    }
    float2 cv = *(const float2*)(cosT + t * DH + e);
    float2 sv = *(const float2*)(sinT + t * DH + e);
    float r0 = xv.x * cv.x + ov.x * sv.x;
    float r1 = xv.y * cv.y + ov.y * sv.y;
    __nv_bfloat162 lo;
    __nv_bfloat162 hi = split2(r0, r1, &lo);
    *(__nv_bfloat162*)(xrh + idx) = hi;
    *(__nv_bfloat162*)(xrl + idx) = lo;
}

// v = LN(v + LN(z0+z1+z2+z3)); also emits v hi/lo splits.
__global__ void fuse_ln4_kernel(const float* __restrict__ z,
                                float* __restrict__ v,
                                __nv_bfloat16* __restrict__ vh,
                                __nv_bfloat16* __restrict__ vl) {
    __shared__ float smem[8];
    int bt = blockIdx.x;
    int d = threadIdx.x;
    long i = (long)bt * DD + d;
    const long S = (long)BB * TT * DD;
    float u = z[i] + z[i + S] + z[i + 2 * S] + z[i + 3 * S];
    float m1 = block_sum_256(u, smem) * (1.0f / DD);
    float c1 = u - m1;
    float var1 = block_sum_256(c1 * c1, smem) * (1.0f / DD);
    float lnz = c1 * rsqrtf(var1 + EPS);
    float w = v[i] + lnz;
    float m2 = block_sum_256(w, smem) * (1.0f / DD);
    float c2 = w - m2;
    float var2 = block_sum_256(c2 * c2, smem) * (1.0f / DD);
    float r = c2 * rsqrtf(var2 + EPS);
    v[i] = r;
    __nv_bfloat16 h = __float2bfloat16(r);
    vh[i] = h;
    vl[i] = __float2bfloat16(r - __bfloat162float(h));
}

// ---------------------------------------------------------------------------
// Host launcher
// ---------------------------------------------------------------------------
#define SMEM_SZ (16 * TILE_B)

template <int EPI, bool ATR, bool BTR, bool OUTS>
static void set_attr() {
    cudaFuncSetAttribute(mm_bf16x3_kernel<EPI, ATR, BTR, OUTS>,
                         cudaFuncAttributeMaxDynamicSharedMemorySize, SMEM_SZ);
}

extern "C" void kernel_launch(void* const* d_in, const int* in_sizes, int n_in,
                              void* d_out, int out_size) {
    const int*   tokens  = (const int*)d_in[0];
    const float* emb_w   = (const float*)d_in[1];
    const float* E       = (const float*)d_in[2];
    const float* Dx      = (const float*)d_in[3];
    const float* Dy      = (const float*)d_in[4];
    const float* readout = (const float*)d_in[5];
    float* out = (float*)d_out;

    float *v, *x, *zb, *cosT, *sinT;
    cudaGetSymbolAddress((void**)&v, g_v);
    cudaGetSymbolAddress((void**)&x, g_x);
    cudaGetSymbolAddress((void**)&zb, g_z);
    cudaGetSymbolAddress((void**)&cosT, g_cos);
    cudaGetSymbolAddress((void**)&sinT, g_sin);

    __nv_bfloat16 *vh, *vl, *xrh, *xrl, *w2h, *w2l, *ah, *al, *yeh, *yel;
    __nv_bfloat16 *dxh, *dxl, *dyh, *dyl, *eh, *el, *roh, *rol;
    cudaGetSymbolAddress((void**)&vh, s_v_hi);   cudaGetSymbolAddress((void**)&vl, s_v_lo);
    cudaGetSymbolAddress((void**)&xrh, s_xr_hi); cudaGetSymbolAddress((void**)&xrl, s_xr_lo);
    cudaGetSymbolAddress((void**)&w2h, s_w2_hi); cudaGetSymbolAddress((void**)&w2l, s_w2_lo);
    cudaGetSymbolAddress((void**)&ah, s_a_hi);   cudaGetSymbolAddress((void**)&al, s_a_lo);
    cudaGetSymbolAddress((void**)&yeh, s_ye_hi); cudaGetSymbolAddress((void**)&yel, s_ye_lo);
    cudaGetSymbolAddress((void**)&dxh, s_dx_hi); cudaGetSymbolAddress((void**)&dxl, s_dx_lo);
    cudaGetSymbolAddress((void**)&dyh, s_dy_hi); cudaGetSymbolAddress((void**)&dyl, s_dy_lo);
    cudaGetSymbolAddress((void**)&eh, s_e_hi);   cudaGetSymbolAddress((void**)&el, s_e_lo);
    cudaGetSymbolAddress((void**)&roh, s_ro_hi); cudaGetSymbolAddress((void**)&rol, s_ro_lo);

    set_attr<1, false, true, false>();
    set_attr<0, true, true, true>();
    set_attr<0, false, false, true>();
    set_attr<2, false, true, true>();
    set_attr<0, false, true, false>();

    rope_tables_kernel<<<TT, 512>>>(cosT, sinT);
    embed_ln_kernel<<<BB * TT, 256>>>(tokens, emb_w, v, vh, vl);

    // Weight splits (once per launch)
    split_kernel<<<(HH * DD * DH) / 1024, 256>>>(Dx, dxh, dxl);
    split_kernel<<<(HH * DD * DH) / 1024, 256>>>(Dy, dyh, dyl);
    split_kernel<<<(NN_ * DD) / 1024, 256>>>(E, eh, el);
    split_kernel<<<(DD * VV) / 1024, 256>>>(readout, roh, rol);

    const long TDh = (long)TT * DH;
    const long TD  = (long)TT * DD;
    const long DDh = (long)DD * DH;
    const long TN  = (long)TT * NN_;

    for (int l = 0; l < LL; l++) {
        // 1) x = relu(v @ Dx_h): M=T N=Dh K=D. fp32 out (needed by rope + AUX).
        mm_bf16x3_kernel<1, false, true, false><<<dim3(8, 8, BB * HH), 256, SMEM_SZ>>>(
            vh, vl, dxh, dxl, x, nullptr, nullptr, nullptr,
            DD, DD, DH, DH, 0,
            HH, TD, 0,   HH, 0, DDh,   1, TDh, 0,   0);

        // 2) RoPE fused with split -> xrh/xrl
        rope_split_kernel<<<(BB * HH * TT * DH) / 512, 256>>>(x, cosT, sinT, xrh, xrl);

        // 3) w2[d,e] = sum_t v[t,d] xr[t,e]: M=D N=Dh K=T -> split out.
        mm_bf16x3_kernel<0, true, true, true><<<dim3(8, 2, BB * HH), 256, SMEM_SZ>>>(
            vh, vl, xrh, xrl, nullptr, w2h, w2l, nullptr,
            TT, DD, DH, DH, 0,
            HH, TD, 0,   1, TDh, 0,   1, DDh, 0,   0);

        // 4) a[t,d] = sum_e xr[t,e] w2[d,e]: M=T N=D K=Dh -> split out.
        mm_bf16x3_kernel<0, false, false, true><<<dim3(2, 8, BB * HH), 256, SMEM_SZ>>>(
            xrh, xrl, w2h, w2l, nullptr, ah, al, nullptr,
            DH, DH, DH, DD, 0,
            1, TDh, 0,   1, DDh, 0,   1, TD, 0,   0);

        // 5) ye = relu(a @ Dy_h) * x: M=T N=Dh K=D -> split out; AUX=x.
        mm_bf16x3_kernel<2, false, true, true><<<dim3(8, 8, BB * HH), 256, SMEM_SZ>>>(
            ah, al, dyh, dyl, nullptr, yeh, yel, x,
            DD, DD, DH, NN_, DH,
            1, TD, 0,   HH, 0, DDh,   HH, TN, DH,   TDh);

        // 6) z partials (split-K x4): M=B*T N=D K=1024 each.
        mm_bf16x3_kernel<0, false, true, false><<<dim3(2, 32, 4), 256, SMEM_SZ>>>(
            yeh, yel, eh, el, zb, nullptr, nullptr, nullptr,
            NN_ / 4, NN_, DD, DD, 0,
            1, NN_ / 4, 0,   1, (long)(NN_ / 4) * DD, 0,   1, (long)BB * TT * DD, 0,   0);

        // 7) v = LN(v + LN(sum z)) + fused v split
        fuse_ln4_kernel<<<BB * TT, 256>>>(zb, v, vh, vl);
    }

    // out = v @ readout: M=B*T N=V K=D.
    mm_bf16x3_kernel<0, false, true, false><<<dim3(2, 32, 1), 256, SMEM_SZ>>>(
        vh, vl, roh, rol, out, nullptr, nullptr, nullptr,
        DD, DD, VV, VV, 0,
        1, 0, 0,   1, 0, 0,   1, 0, 0,   0);
}

// round 9
// speedup vs baseline: 4.6787x; 1.0845x over previous
#include <cuda_runtime.h>
#include <cuda_bf16.h>
#include <math.h>
#include <stdint.h>

// Problem constants
#define BB 4
#define TT 1024
#define HH 4
#define NN_ 4096
#define DD 256
#define DH 1024
#define LL 6
#define VV 256
#define EPS 1e-5f

// ---------------------------------------------------------------------------
// Scratch buffers (device globals; no allocation allowed)
// ---------------------------------------------------------------------------
__device__ float g_v[BB * TT * DD];
__device__ float g_x[BB * HH * TT * DH];
__device__ float g_z[4 * BB * TT * DD];     // split-K partials
__device__ float g_cos[TT * DH];
__device__ float g_sin[TT * DH];

// bf16 hi/lo split operand buffers
__device__ __nv_bfloat16 s_v_hi[BB * TT * DD],   s_v_lo[BB * TT * DD];
__device__ __nv_bfloat16 s_xr_hi[BB * HH * TT * DH], s_xr_lo[BB * HH * TT * DH];
__device__ __nv_bfloat16 s_w2_hi[BB * HH * DD * DH], s_w2_lo[BB * HH * DD * DH];
__device__ __nv_bfloat16 s_a_hi[BB * HH * TT * DD],  s_a_lo[BB * HH * TT * DD];
__device__ __nv_bfloat16 s_ye_hi[BB * TT * NN_], s_ye_lo[BB * TT * NN_];
__device__ __nv_bfloat16 s_dx_hi[HH * DD * DH],  s_dx_lo[HH * DD * DH];
__device__ __nv_bfloat16 s_dy_hi[HH * DD * DH],  s_dy_lo[HH * DD * DH];
__device__ __nv_bfloat16 s_e_hi[NN_ * DD],       s_e_lo[NN_ * DD];
__device__ __nv_bfloat16 s_ro_hi[DD * VV],       s_ro_lo[DD * VV];

// ---------------------------------------------------------------------------
// PTX helpers
// ---------------------------------------------------------------------------
__device__ __forceinline__ uint32_t smem_to_u32(const void* p) {
    uint32_t a;
    asm("{ .reg .u64 t; cvta.to.shared.u64 t, %1; cvt.u32.u64 %0, t; }" : "=r"(a) : "l"(p));
    return a;
}
__device__ __forceinline__ void cp16(uint32_t dst, const void* src) {
    asm volatile("cp.async.cg.shared.global [%0], [%1], 16;" :: "r"(dst), "l"(src));
}
#define CP_COMMIT() asm volatile("cp.async.commit_group;" ::: "memory")
#define CP_WAIT0() asm volatile("cp.async.wait_group 0;" ::: "memory")
#define CP_WAIT1() asm volatile("cp.async.wait_group 1;" ::: "memory")

__device__ __forceinline__ void ldsm_x4(uint32_t* r, uint32_t addr) {
    asm volatile("ldmatrix.sync.aligned.m8n8.x4.shared.b16 {%0,%1,%2,%3}, [%4];"
                 : "=r"(r[0]), "=r"(r[1]), "=r"(r[2]), "=r"(r[3]) : "r"(addr));
}
__device__ __forceinline__ void ldsm_x4_t(uint32_t* r, uint32_t addr) {
    asm volatile("ldmatrix.sync.aligned.m8n8.x4.trans.shared.b16 {%0,%1,%2,%3}, [%4];"
                 : "=r"(r[0]), "=r"(r[1]), "=r"(r[2]), "=r"(r[3]) : "r"(addr));
}
__device__ __forceinline__ void mma_bf16(float* d, const uint32_t* a, const uint32_t* b) {
    asm volatile(
        "mma.sync.aligned.m16n8k16.row.col.f32.bf16.bf16.f32 "
        "{%0,%1,%2,%3}, {%4,%5,%6,%7}, {%8,%9}, {%0,%1,%2,%3};"
        : "+f"(d[0]), "+f"(d[1]), "+f"(d[2]), "+f"(d[3])
        : "r"(a[0]), "r"(a[1]), "r"(a[2]), "r"(a[3]), "r"(b[0]), "r"(b[1]));
}
__device__ __forceinline__ __nv_bfloat162 split2(float x, float y,
                                                 __nv_bfloat162* lo) {
    __nv_bfloat16 hx = __float2bfloat16(x);
    __nv_bfloat16 hy = __float2bfloat16(y);
    *lo = __halves2bfloat162(__float2bfloat16(x - __bfloat162float(hx)),
                             __float2bfloat16(y - __bfloat162float(hy)));
    return __halves2bfloat162(hx, hy);
}

// ---------------------------------------------------------------------------
// bf16x3 GEMM: C = epi(A @ B^T), 128x128 CTA tile, 8 warps (2x4), K-stage 32.
//   A arrays: ATR=false -> [M,K]; ATR=true -> [K,M].
//   B arrays: BTR=false -> [N,K]; BTR=true -> [K,N].
//   EPI 0: acc; 1: relu; 2: relu*AUX.
//   OUTSPLIT: write bf16 hi/lo pair (Chi/Clo) instead of fp32 C.
// 3-stage cp.async pipeline, ONE __syncthreads per K-stage.
// ---------------------------------------------------------------------------
#define TILE_B 4096
#define NBUF 3
__device__ __forceinline__ uint32_t tile_addr(uint32_t sb, int buf, int ab, int sub, int hl) {
    return sb + (uint32_t)((((buf * 2 + ab) * 2 + sub) * 2 + hl) * TILE_B);
}

template <int EPI, bool ATR, bool BTR, bool OUTSPLIT>
__global__ void __launch_bounds__(256)
mm_bf16x3_kernel(const __nv_bfloat16* __restrict__ Ahi, const __nv_bfloat16* __restrict__ Alo,
                 const __nv_bfloat16* __restrict__ Bhi, const __nv_bfloat16* __restrict__ Blo,
                 float* __restrict__ C,
                 __nv_bfloat16* __restrict__ Chi, __nv_bfloat16* __restrict__ Clo,
                 const float* __restrict__ AUX,
                 int K, int lda, int ldb, int ldc, int ldaux,
                 int divA, long sA1, long sA2,
                 int divB, long sB1, long sB2,
                 int divC, long sC1, long sC2,
                 long sAux) {
    extern __shared__ char smem[];
    const uint32_t sb = smem_to_u32(smem);
    const int tid = threadIdx.x;
    const int wid = tid >> 5;
    const int lane = tid & 31;
    const int wr = wid >> 2;
    const int wc = wid & 3;
    const int g = lane >> 2;
    const int tig = lane & 3;

    const int z = blockIdx.z;
    const long offA = (long)(z / divA) * sA1 + (long)(z % divA) * sA2;
    const long offB = (long)(z / divB) * sB1 + (long)(z % divB) * sB2;
    const long offC = (long)(z / divC) * sC1 + (long)(z % divC) * sC2;
    Ahi += offA; Alo += offA; Bhi += offB; Blo += offB;
    if (!OUTSPLIT) C += offC; else { Chi += offC; Clo += offC; }
    if (EPI == 2) AUX += (long)z * sAux;
    const int rowBase = blockIdx.y * 128;
    const int colBase = blockIdx.x * 128;

    // staging constants
    const int nr = tid >> 1, nh = tid & 1;                 // normal: row, 16B-half
    const uint32_t ndst = (uint32_t)(nr * 32 + 16 * (nh ^ ((nr >> 2) & 1)));
    const int tkr = tid >> 4, tnb = tid & 15;              // trans: k-row, n-block
    const uint32_t tdst = (uint32_t)(tkr * 256 + 16 * ((tnb ^ (tkr & 7)) & 15));

    float acc[4][4][4];
    #pragma unroll
    for (int i = 0; i < 4; i++)
        #pragma unroll
        for (int j = 0; j < 4; j++)
            #pragma unroll
            for (int k = 0; k < 4; k++) acc[i][j][k] = 0.0f;

    const int nStages = K >> 5;

    auto stage = [&](int buf, int c) {
        const int k0 = c << 5;
        #pragma unroll
        for (int sub = 0; sub < 2; sub++) {
            if (!ATR) {
                long src = (long)(rowBase + nr) * lda + k0 + sub * 16 + 8 * nh;
                cp16(tile_addr(sb, buf, 0, sub, 0) + ndst, Ahi + src);
                cp16(tile_addr(sb, buf, 0, sub, 1) + ndst, Alo + src);
            } else {
                long src = (long)(k0 + sub * 16 + tkr) * lda + rowBase + 8 * tnb;
                cp16(tile_addr(sb, buf, 0, sub, 0) + tdst, Ahi + src);
                cp16(tile_addr(sb, buf, 0, sub, 1) + tdst, Alo + src);
            }
            if (!BTR) {
                long src = (long)(colBase + nr) * ldb + k0 + sub * 16 + 8 * nh;
                cp16(tile_addr(sb, buf, 1, sub, 0) + ndst, Bhi + src);
                cp16(tile_addr(sb, buf, 1, sub, 1) + ndst, Blo + src);
            } else {
                long src = (long)(k0 + sub * 16 + tkr) * ldb + colBase + 8 * tnb;
                cp16(tile_addr(sb, buf, 1, sub, 0) + tdst, Bhi + src);
                cp16(tile_addr(sb, buf, 1, sub, 1) + tdst, Blo + src);
            }
        }
    };

    auto compute = [&](int buf) {
        #pragma unroll
        for (int sub = 0; sub < 2; sub++) {
            uint32_t afr[2][4][4], bfr[2][4][2];
            #pragma unroll
            for (int hl = 0; hl < 2; hl++) {
                const uint32_t tb = tile_addr(sb, buf, 0, sub, hl);
                if (!ATR) {
                    const int rl = (lane & 7) + 8 * ((lane >> 3) & 1);
                    const int h = lane >> 4;
                    const uint32_t lo32 = (uint32_t)(rl * 32 + 16 * (h ^ ((rl >> 2) & 1)));
                    #pragma unroll
                    for (int ms = 0; ms < 4; ms++)
                        ldsm_x4(&afr[hl][ms][0], tb + (uint32_t)((wr * 64 + ms * 16) * 32) + lo32);
                } else {
                    const int kr = (lane & 7) + 8 * (lane >> 4);
                    const int mb0 = wr * 8 + ((lane >> 3) & 1);
                    #pragma unroll
                    for (int ms = 0; ms < 4; ms++) {
                        const int mb = mb0 + ms * 2;
                        ldsm_x4_t(&afr[hl][ms][0],
                                  tb + (uint32_t)(kr * 256 + 16 * ((mb ^ (kr & 7)) & 15)));
                    }
                }
            }
            #pragma unroll
            for (int hl = 0; hl < 2; hl++) {
                const uint32_t tb = tile_addr(sb, buf, 1, sub, hl);
                if (!BTR) {
                    const int rl = (lane >> 4) * 8 + (lane & 7);
                    const int h = (lane >> 3) & 1;
                    const uint32_t lo32 = (uint32_t)(rl * 32 + 16 * (h ^ ((rl >> 2) & 1)));
                    #pragma unroll
                    for (int p = 0; p < 2; p++) {
                        uint32_t r4[4];
                        ldsm_x4(r4, tb + (uint32_t)((wc * 32 + p * 16) * 32) + lo32);
                        bfr[hl][2 * p][0] = r4[0]; bfr[hl][2 * p][1] = r4[1];
                        bfr[hl][2 * p + 1][0] = r4[2]; bfr[hl][2 * p + 1][1] = r4[3];
                    }
                } else {
                    const int kr = (lane & 7) + 8 * ((lane >> 3) & 1);
                    const int nb0 = wc * 4 + (lane >> 4);
                    #pragma unroll
                    for (int p = 0; p < 2; p++) {
                        const int nb = nb0 + p * 2;
                        uint32_t r4[4];
                        ldsm_x4_t(r4, tb + (uint32_t)(kr * 256 + 16 * ((nb ^ (kr & 7)) & 15)));
                        bfr[hl][2 * p][0] = r4[0]; bfr[hl][2 * p][1] = r4[1];
                        bfr[hl][2 * p + 1][0] = r4[2]; bfr[hl][2 * p + 1][1] = r4[3];
                    }
                }
            }
            #pragma unroll
            for (int ms = 0; ms < 4; ms++)
                #pragma unroll
                for (int ns = 0; ns < 4; ns++)
                    mma_bf16(acc[ms][ns], afr[0][ms], bfr[0][ns]);
            #pragma unroll
            for (int ms = 0; ms < 4; ms++)
                #pragma unroll
                for (int ns = 0; ns < 4; ns++)
                    mma_bf16(acc[ms][ns], afr[0][ms], bfr[1][ns]);
            #pragma unroll
            for (int ms = 0; ms < 4; ms++)
                #pragma unroll
                for (int ns = 0; ns < 4; ns++)
                    mma_bf16(acc[ms][ns], afr[1][ms], bfr[0][ns]);
        }
    };

    // 3-stage pipeline, one sync per stage.
    stage(0, 0); CP_COMMIT();
    stage(1, 1); CP_COMMIT();
    int buf = 0;
    for (int c = 0; c < nStages; c++) {
        if (c < nStages - 1) { CP_WAIT1(); } else { CP_WAIT0(); }
        __syncthreads();
        compute(buf);
        if (c + 2 < nStages) {
            int nb = buf + 2; if (nb >= NBUF) nb -= NBUF;
            stage(nb, c + 2);
            CP_COMMIT();
        }
        if (++buf == NBUF) buf = 0;
    }

    // Epilogue
    #pragma unroll
    for (int ms = 0; ms < 4; ms++) {
        const int r = rowBase + wr * 64 + ms * 16 + g;
        #pragma unroll
        for (int ns = 0; ns < 4; ns++) {
            const int col = colBase + wc * 32 + ns * 8 + tig * 2;
            float2 v0 = make_float2(acc[ms][ns][0], acc[ms][ns][1]);
            float2 v1 = make_float2(acc[ms][ns][2], acc[ms][ns][3]);
            if (EPI >= 1) {
                v0.x = fmaxf(v0.x, 0.0f); v0.y = fmaxf(v0.y, 0.0f);
                v1.x = fmaxf(v1.x, 0.0f); v1.y = fmaxf(v1.y, 0.0f);
            }
            if (EPI == 2) {
                float2 a0 = *(const float2*)(AUX + (long)r * ldaux + col);
                float2 a1 = *(const float2*)(AUX + (long)(r + 8) * ldaux + col);
                v0.x *= a0.x; v0.y *= a0.y;
                v1.x *= a1.x; v1.y *= a1.y;
            }
            if (!OUTSPLIT) {
                *(float2*)(C + (long)r * ldc + col) = v0;
                *(float2*)(C + (long)(r + 8) * ldc + col) = v1;
            } else {
                __nv_bfloat162 lo0, lo1;
                __nv_bfloat162 hi0 = split2(v0.x, v0.y, &lo0);
                __nv_bfloat162 hi1 = split2(v1.x, v1.y, &lo1);
                *(__nv_bfloat162*)(Chi + (long)r * ldc + col) = hi0;
                *(__nv_bfloat162*)(Clo + (long)r * ldc + col) = lo0;
                *(__nv_bfloat162*)(Chi + (long)(r + 8) * ldc + col) = hi1;
                *(__nv_bfloat162*)(Clo + (long)(r + 8) * ldc + col) = lo1;
            }
        }
    }
}

// ---------------------------------------------------------------------------
// Split: fp32 -> bf16 hi + bf16 lo (weights, once per launch)
// ---------------------------------------------------------------------------
__global__ void split_kernel(const float* __restrict__ in,
                             __nv_bfloat16* __restrict__ hi,
                             __nv_bfloat16* __restrict__ lo) {
    long i = ((long)blockIdx.x * blockDim.x + threadIdx.x) * 4;
    float4 v = *(const float4*)(in + i);
    __nv_bfloat162 l0, l1;
    __nv_bfloat162 h0 = split2(v.x, v.y, &l0);
    __nv_bfloat162 h1 = split2(v.z, v.w, &l1);
    __nv_bfloat162* hp = (__nv_bfloat162*)(hi + i);
    __nv_bfloat162* lp = (__nv_bfloat162*)(lo + i);
    hp[0] = h0; hp[1] = h1;
    lp[0] = l0; lp[1] = l1;
}

// ---------------------------------------------------------------------------
// Elementwise kernels
// ---------------------------------------------------------------------------
__device__ __forceinline__ float block_sum_256(float v, float* smem) {
    #pragma unroll
    for (int o = 16; o > 0; o >>= 1) v += __shfl_down_sync(0xffffffffu, v, o);
    int w = threadIdx.x >> 5, l = threadIdx.x & 31;
    if (l == 0) smem[w] = v;
    __syncthreads();
    if (w == 0) {
        float s = (l < 8) ? smem[l] : 0.0f;
        #pragma unroll
        for (int o = 4; o > 0; o >>= 1) s += __shfl_down_sync(0xffffffffu, s, o);
        if (l == 0) smem[0] = s;
    }
    __syncthreads();
    float r = smem[0];
    __syncthreads();
    return r;
}

__global__ void rope_tables_kernel(float* cosT, float* sinT) {
    int t = blockIdx.x;
    int j = threadIdx.x;
    double expnt = (2.0 * (double)j) / (double)DH;
    double inv = pow(10000.0, -expnt);
    double phase = (double)t * inv;
    float c = (float)cos(phase);
    float s = (float)sin(phase);
    cosT[t * DH + j] = c;  cosT[t * DH + 512 + j] = c;
    sinT[t * DH + j] = s;  sinT[t * DH + 512 + j] = s;
}

__global__ void embed_ln_kernel(const int* __restrict__ tokens,
                                const float* __restrict__ emb_w,
                                float* __restrict__ v,
                                __nv_bfloat16* __restrict__ vh,
                                __nv_bfloat16* __restrict__ vl) {
    __shared__ float smem[8];
    int bt = blockIdx.x;
    int d = threadIdx.x;
    int tok = tokens[bt];
    float val = emb_w[tok * DD + d];
    float m = block_sum_256(val, smem) * (1.0f / DD);
    float c = val - m;
    float var = block_sum_256(c * c, smem) * (1.0f / DD);
    float r = c * rsqrtf(var + EPS);
    v[bt * DD + d] = r;
    __nv_bfloat16 h = __float2bfloat16(r);
    vh[bt * DD + d] = h;
    vl[bt * DD + d] = __float2bfloat16(r - __bfloat162float(h));
}

// RoPE fused with split: reads x fp32, writes xr hi/lo bf16 directly.
__global__ void rope_split_kernel(const float* __restrict__ x,
                                  const float* __restrict__ cosT,
                                  const float* __restrict__ sinT,
                                  __nv_bfloat16* __restrict__ xrh,
                                  __nv_bfloat16* __restrict__ xrl) {
    long idx = ((long)blockIdx.x * blockDim.x + threadIdx.x) * 2;
    int e = (int)(idx & (DH - 1));
    int t = (int)((idx >> 10) & (TT - 1));
    float2 xv = *(const float2*)(x + idx);
    float2 ov;
    if (e < 512) {
        ov = *(const float2*)(x + idx + 512);
        ov.x = -ov.x; ov.y = -ov.y;
    } else {
        ov = *(const float2*)(x + idx - 512);
    }
    float2 cv = *(const float2*)(cosT + t * DH + e);
    float2 sv = *(const float2*)(sinT + t * DH + e);
    float r0 = xv.x * cv.x + ov.x * sv.x;
    float r1 = xv.y * cv.y + ov.y * sv.y;
    __nv_bfloat162 lo;
    __nv_bfloat162 hi = split2(r0, r1, &lo);
    *(__nv_bfloat162*)(xrh + idx) = hi;
    *(__nv_bfloat162*)(xrl + idx) = lo;
}

// v = LN(v + LN(z0+z1+z2+z3)); also emits v hi/lo splits.
__global__ void fuse_ln4_kernel(const float* __restrict__ z,
                                float* __restrict__ v,
                                __nv_bfloat16* __restrict__ vh,
                                __nv_bfloat16* __restrict__ vl) {
    __shared__ float smem[8];
    int bt = blockIdx.x;
    int d = threadIdx.x;
    long i = (long)bt * DD + d;
    const long S = (long)BB * TT * DD;
    float u = z[i] + z[i + S] + z[i + 2 * S] + z[i + 3 * S];
    float m1 = block_sum_256(u, smem) * (1.0f / DD);
    float c1 = u - m1;
    float var1 = block_sum_256(c1 * c1, smem) * (1.0f / DD);
    float lnz = c1 * rsqrtf(var1 + EPS);
    float w = v[i] + lnz;
    float m2 = block_sum_256(w, smem) * (1.0f / DD);
    float c2 = w - m2;
    float var2 = block_sum_256(c2 * c2, smem) * (1.0f / DD);
    float r = c2 * rsqrtf(var2 + EPS);
    v[i] = r;
    __nv_bfloat16 h = __float2bfloat16(r);
    vh[i] = h;
    vl[i] = __float2bfloat16(r - __bfloat162float(h));
}

// ---------------------------------------------------------------------------
// Host launcher
// ---------------------------------------------------------------------------
#define SMEM_SZ (NBUF * 8 * TILE_B)

template <int EPI, bool ATR, bool BTR, bool OUTS>
static void set_attr() {
    cudaFuncSetAttribute(mm_bf16x3_kernel<EPI, ATR, BTR, OUTS>,
                         cudaFuncAttributeMaxDynamicSharedMemorySize, SMEM_SZ);
}

extern "C" void kernel_launch(void* const* d_in, const int* in_sizes, int n_in,
                              void* d_out, int out_size) {
    const int*   tokens  = (const int*)d_in[0];
    const float* emb_w   = (const float*)d_in[1];
    const float* E       = (const float*)d_in[2];
    const float* Dx      = (const float*)d_in[3];
    const float* Dy      = (const float*)d_in[4];
    const float* readout = (const float*)d_in[5];
    float* out = (float*)d_out;

    float *v, *x, *zb, *cosT, *sinT;
    cudaGetSymbolAddress((void**)&v, g_v);
    cudaGetSymbolAddress((void**)&x, g_x);
    cudaGetSymbolAddress((void**)&zb, g_z);
    cudaGetSymbolAddress((void**)&cosT, g_cos);
    cudaGetSymbolAddress((void**)&sinT, g_sin);

    __nv_bfloat16 *vh, *vl, *xrh, *xrl, *w2h, *w2l, *ah, *al, *yeh, *yel;
    __nv_bfloat16 *dxh, *dxl, *dyh, *dyl, *eh, *el, *roh, *rol;
    cudaGetSymbolAddress((void**)&vh, s_v_hi);   cudaGetSymbolAddress((void**)&vl, s_v_lo);
    cudaGetSymbolAddress((void**)&xrh, s_xr_hi); cudaGetSymbolAddress((void**)&xrl, s_xr_lo);
    cudaGetSymbolAddress((void**)&w2h, s_w2_hi); cudaGetSymbolAddress((void**)&w2l, s_w2_lo);
    cudaGetSymbolAddress((void**)&ah, s_a_hi);   cudaGetSymbolAddress((void**)&al, s_a_lo);
    cudaGetSymbolAddress((void**)&yeh, s_ye_hi); cudaGetSymbolAddress((void**)&yel, s_ye_lo);
    cudaGetSymbolAddress((void**)&dxh, s_dx_hi); cudaGetSymbolAddress((void**)&dxl, s_dx_lo);
    cudaGetSymbolAddress((void**)&dyh, s_dy_hi); cudaGetSymbolAddress((void**)&dyl, s_dy_lo);
    cudaGetSymbolAddress((void**)&eh, s_e_hi);   cudaGetSymbolAddress((void**)&el, s_e_lo);
    cudaGetSymbolAddress((void**)&roh, s_ro_hi); cudaGetSymbolAddress((void**)&rol, s_ro_lo);

    set_attr<1, false, true, false>();
    set_attr<0, true, true, true>();
    set_attr<0, false, false, true>();
    set_attr<2, false, true, true>();
    set_attr<0, false, true, false>();

    rope_tables_kernel<<<TT, 512>>>(cosT, sinT);
    embed_ln_kernel<<<BB * TT, 256>>>(tokens, emb_w, v, vh, vl);

    // Weight splits (once per launch)
    split_kernel<<<(HH * DD * DH) / 1024, 256>>>(Dx, dxh, dxl);
    split_kernel<<<(HH * DD * DH) / 1024, 256>>>(Dy, dyh, dyl);
    split_kernel<<<(NN_ * DD) / 1024, 256>>>(E, eh, el);
    split_kernel<<<(DD * VV) / 1024, 256>>>(readout, roh, rol);

    const long TDh = (long)TT * DH;
    const long TD  = (long)TT * DD;
    const long DDh = (long)DD * DH;
    const long TN  = (long)TT * NN_;

    for (int l = 0; l < LL; l++) {
        // 1) x = relu(v @ Dx_h): M=T N=Dh K=D. fp32 out (needed by rope + AUX).
        mm_bf16x3_kernel<1, false, true, false><<<dim3(8, 8, BB * HH), 256, SMEM_SZ>>>(
            vh, vl, dxh, dxl, x, nullptr, nullptr, nullptr,
            DD, DD, DH, DH, 0,
            HH, TD, 0,   HH, 0, DDh,   1, TDh, 0,   0);

        // 2) RoPE fused with split -> xrh/xrl
        rope_split_kernel<<<(BB * HH * TT * DH) / 512, 256>>>(x, cosT, sinT, xrh, xrl);

        // 3) w2[d,e] = sum_t v[t,d] xr[t,e]: M=D N=Dh K=T -> split out.
        mm_bf16x3_kernel<0, true, true, true><<<dim3(8, 2, BB * HH), 256, SMEM_SZ>>>(
            vh, vl, xrh, xrl, nullptr, w2h, w2l, nullptr,
            TT, DD, DH, DH, 0,
            HH, TD, 0,   1, TDh, 0,   1, DDh, 0,   0);

        // 4) a[t,d] = sum_e xr[t,e] w2[d,e]: M=T N=D K=Dh -> split out.
        mm_bf16x3_kernel<0, false, false, true><<<dim3(2, 8, BB * HH), 256, SMEM_SZ>>>(
            xrh, xrl, w2h, w2l, nullptr, ah, al, nullptr,
            DH, DH, DH, DD, 0,
            1, TDh, 0,   1, DDh, 0,   1, TD, 0,   0);

        // 5) ye = relu(a @ Dy_h) * x: M=T N=Dh K=D -> split out; AUX=x.
        mm_bf16x3_kernel<2, false, true, true><<<dim3(8, 8, BB * HH), 256, SMEM_SZ>>>(
            ah, al, dyh, dyl, nullptr, yeh, yel, x,
            DD, DD, DH, NN_, DH,
            1, TD, 0,   HH, 0, DDh,   HH, TN, DH,   TDh);

        // 6) z partials (split-K x4): M=B*T N=D K=1024 each.
        mm_bf16x3_kernel<0, false, true, false><<<dim3(2, 32, 4), 256, SMEM_SZ>>>(
            yeh, yel, eh, el, zb, nullptr, nullptr, nullptr,
            NN_ / 4, NN_, DD, DD, 0,
            1, NN_ / 4, 0,   1, (long)(NN_ / 4) * DD, 0,   1, (long)BB * TT * DD, 0,   0);

        // 7) v = LN(v + LN(sum z)) + fused v split
        fuse_ln4_kernel<<<BB * TT, 256>>>(zb, v, vh, vl);
    }

    // out = v @ readout: M=B*T N=V K=D.
    mm_bf16x3_kernel<0, false, true, false><<<dim3(2, 32, 1), 256, SMEM_SZ>>>(
        vh, vl, roh, rol, out, nullptr, nullptr, nullptr,
        DD, DD, VV, VV, 0,
        1, 0, 0,   1, 0, 0,   1, 0, 0,   0);
}